// round 1
// baseline (speedup 1.0000x reference)
#include <cuda_runtime.h>
#include <cstdint>

// Problem constants
#define T_TOKENS 2048
#define DIM_     2048
#define HID_     5632
#define NEXP     8
#define NENT     (T_TOKENS * 2)   // total (token, expert) assignments: top-2

// ---------------------------------------------------------------------------
// Scratch (device globals — no cudaMalloc allowed)
// ---------------------------------------------------------------------------
__device__ int   g_eid [T_TOKENS][2];   // top-2 expert ids per token
__device__ float g_ew  [T_TOKENS][2];   // softmaxed combine weights
__device__ int   g_pos [T_TOKENS][2];   // position of token within its expert's list
__device__ int   g_list[NEXP][T_TOKENS];// token ids per expert (compact)
__device__ int   g_cnt [NEXP];
__device__ int   g_off [NEXP];          // exclusive prefix of counts -> entry base
__device__ float g_h   [(size_t)NENT * HID_];  // 92 MB: SwiGLU hidden per entry
__device__ float g_y   [(size_t)NENT * DIM_];  // 33 MB: per-entry FFN output

// ---------------------------------------------------------------------------
// f32x2 packed-FMA helpers (fma.rn.f32x2 doubles fp32 FMA throughput on sm_103a)
// ---------------------------------------------------------------------------
__device__ __forceinline__ unsigned long long pk2(float lo, float hi) {
    unsigned long long r;
    asm("mov.b64 %0, {%1, %2};" : "=l"(r)
        : "r"(__float_as_uint(lo)), "r"(__float_as_uint(hi)));
    return r;
}
__device__ __forceinline__ void upk2(unsigned long long v, float& lo, float& hi) {
    unsigned a, b;
    asm("mov.b64 {%0, %1}, %2;" : "=r"(a), "=r"(b) : "l"(v));
    lo = __uint_as_float(a);
    hi = __uint_as_float(b);
}
__device__ __forceinline__ void fma2(unsigned long long& acc,
                                     unsigned long long a, unsigned long long b) {
    asm("fma.rn.f32x2 %0, %1, %2, %0;" : "+l"(acc) : "l"(a), "l"(b));
}

// ---------------------------------------------------------------------------
// Kernel 1: gating scores + top-2 + softmax.  One block per token, 8 warps:
// warp w computes dot(x[t], gate_w[w]).
// ---------------------------------------------------------------------------
__global__ void gate_kernel(const float* __restrict__ x,
                            const float* __restrict__ gw) {
    const int t    = blockIdx.x;
    const int lane = threadIdx.x & 31;
    const int w    = threadIdx.x >> 5;

    const float* xr = x  + (size_t)t * DIM_;
    const float* gr = gw + (size_t)w * DIM_;

    float s = 0.f;
    for (int d = lane * 4; d < DIM_; d += 32 * 4) {
        float4 a = *(const float4*)(xr + d);
        float4 b = *(const float4*)(gr + d);
        s += a.x * b.x + a.y * b.y + a.z * b.z + a.w * b.w;
    }
    #pragma unroll
    for (int o = 16; o; o >>= 1) s += __shfl_xor_sync(0xffffffffu, s, o);

    __shared__ float sc[NEXP];
    if (lane == 0) sc[w] = s;
    __syncthreads();

    if (threadIdx.x == 0) {
        // top-1 (lowest index wins ties, matching jax top_k)
        int b0 = 0; float s0 = sc[0];
        #pragma unroll
        for (int e = 1; e < NEXP; e++) if (sc[e] > s0) { s0 = sc[e]; b0 = e; }
        // top-2
        int b1 = -1; float s1 = -1e30f;
        #pragma unroll
        for (int e = 0; e < NEXP; e++)
            if (e != b0 && sc[e] > s1) { s1 = sc[e]; b1 = e; }
        // softmax over [s0, s1] (s0 >= s1)
        float e1  = __expf(s1 - s0);
        float inv = 1.f / (1.f + e1);
        g_eid[t][0] = b0; g_eid[t][1] = b1;
        g_ew [t][0] = inv; g_ew [t][1] = e1 * inv;
    }
}

// ---------------------------------------------------------------------------
// Kernel 2: build deterministic per-expert token lists (warp-scan, no atomics).
// One block, warp e scans all tokens in order for expert e.
// ---------------------------------------------------------------------------
__global__ void route_kernel() {
    const int lane = threadIdx.x & 31;
    const int e    = threadIdx.x >> 5;
    if (e < NEXP) {
        int cnt = 0;
        for (int t0 = 0; t0 < T_TOKENS; t0 += 32) {
            int  t   = t0 + lane;
            int  e0  = g_eid[t][0];
            int  e1  = g_eid[t][1];
            bool sel = (e0 == e) || (e1 == e);
            int  slot = (e0 == e) ? 0 : 1;
            unsigned m = __ballot_sync(0xffffffffu, sel);
            if (sel) {
                int p = cnt + __popc(m & ((1u << lane) - 1u));
                g_list[e][p]   = t;
                g_pos[t][slot] = p;
            }
            cnt += __popc(m);
        }
        if (lane == 0) g_cnt[e] = cnt;
    }
    __syncthreads();
    if (threadIdx.x == 0) {
        int off = 0;
        #pragma unroll
        for (int i = 0; i < NEXP; i++) { g_off[i] = off; off += g_cnt[i]; }
    }
}

// ---------------------------------------------------------------------------
// Kernel 3: grouped GEMM1, fused:  h = silu(x @ w1[e]) * (x @ w3[e])
// Tile: 128 tokens x 64 hidden cols, computing both w1 and w3 contributions
// (128 effective B columns).  256 threads, 8x(4+4) microtile, f32x2 FMAs.
// ---------------------------------------------------------------------------
__global__ __launch_bounds__(256, 2)
void ffn1_kernel(const float* __restrict__ x,
                 const float* __restrict__ w1,
                 const float* __restrict__ w3) {
    const int e   = blockIdx.z;
    const int cnt = g_cnt[e];
    const int m0  = blockIdx.y * 128;
    if (m0 >= cnt) return;
    const int n0   = blockIdx.x * 64;
    const int base = g_off[e];

    __shared__ float As[16][132];   // [k][m], padded
    __shared__ float Bs[16][132];   // [k][0..63]=w1 cols, [64..127]=w3 cols

    const int tid = threadIdx.x;
    const int tx  = tid & 15;
    const int ty  = tid >> 4;

    // A-load mapping: 512 float4 = 128 rows x 4 quads; 2 per thread
    int rowm[2];
    const float* aptr[2];
    #pragma unroll
    for (int q = 0; q < 2; q++) {
        int idx = tid * 2 + q;
        int m   = idx >> 2;
        int gm  = m0 + m;
        int tk  = g_list[e][min(gm, cnt - 1)];
        rowm[q] = m;
        aptr[q] = x + (size_t)tk * DIM_ + (idx & 3) * 4;
    }
    // B-load mapping: 16 k-rows x 16 float4 per matrix; 1 f4 from each of w1,w3
    const int kb = tid >> 4;
    const int nf = tid & 15;
    const float* b1p = w1 + ((size_t)e * DIM_ + kb) * HID_ + n0 + nf * 4;
    const float* b3p = w3 + ((size_t)e * DIM_ + kb) * HID_ + n0 + nf * 4;

    unsigned long long au[8][2], av[8][2];
    #pragma unroll
    for (int i = 0; i < 8; i++) { au[i][0] = au[i][1] = av[i][0] = av[i][1] = 0ull; }

    for (int k0 = 0; k0 < DIM_; k0 += 16) {
        #pragma unroll
        for (int q = 0; q < 2; q++) {
            float4 v = *(const float4*)(aptr[q] + k0);
            int kq = ((tid * 2 + q) & 3) * 4;
            As[kq + 0][rowm[q]] = v.x;
            As[kq + 1][rowm[q]] = v.y;
            As[kq + 2][rowm[q]] = v.z;
            As[kq + 3][rowm[q]] = v.w;
        }
        {
            float4 v1 = *(const float4*)(b1p + (size_t)k0 * HID_);
            float4 v3 = *(const float4*)(b3p + (size_t)k0 * HID_);
            *(float4*)&Bs[kb][nf * 4]      = v1;
            *(float4*)&Bs[kb][64 + nf * 4] = v3;
        }
        __syncthreads();
        #pragma unroll
        for (int k = 0; k < 16; k++) {
            float4 a0 = *(const float4*)&As[k][ty * 8];
            float4 a1 = *(const float4*)&As[k][ty * 8 + 4];
            ulonglong2 bu = *(const ulonglong2*)&Bs[k][tx * 4];
            ulonglong2 bv = *(const ulonglong2*)&Bs[k][64 + tx * 4];
            float a[8] = {a0.x, a0.y, a0.z, a0.w, a1.x, a1.y, a1.z, a1.w};
            #pragma unroll
            for (int i = 0; i < 8; i++) {
                unsigned long long ad = pk2(a[i], a[i]);
                fma2(au[i][0], ad, bu.x);
                fma2(au[i][1], ad, bu.y);
                fma2(av[i][0], ad, bv.x);
                fma2(av[i][1], ad, bv.y);
            }
        }
        __syncthreads();
    }

    // epilogue: h = silu(u) * v
    #pragma unroll
    for (int i = 0; i < 8; i++) {
        int gm = m0 + ty * 8 + i;
        if (gm < cnt) {
            float u0, u1, u2, u3, v0, v1, v2, v3;
            upk2(au[i][0], u0, u1); upk2(au[i][1], u2, u3);
            upk2(av[i][0], v0, v1); upk2(av[i][1], v2, v3);
            float4 hv;
            hv.x = u0 / (1.f + __expf(-u0)) * v0;
            hv.y = u1 / (1.f + __expf(-u1)) * v1;
            hv.z = u2 / (1.f + __expf(-u2)) * v2;
            hv.w = u3 / (1.f + __expf(-u3)) * v3;
            *(float4*)&g_h[(size_t)(base + gm) * HID_ + n0 + tx * 4] = hv;
        }
    }
}

// ---------------------------------------------------------------------------
// Kernel 4: grouped GEMM2:  y = h @ w2[e]   (weights applied later in combine)
// Tile: 128 entries x 128 out cols, K=HID.  256 threads, 8x8, f32x2.
// ---------------------------------------------------------------------------
__global__ __launch_bounds__(256, 2)
void ffn2_kernel(const float* __restrict__ w2) {
    const int e   = blockIdx.z;
    const int cnt = g_cnt[e];
    const int m0  = blockIdx.y * 128;
    if (m0 >= cnt) return;
    const int n0   = blockIdx.x * 128;
    const int base = g_off[e];

    __shared__ float As[16][132];
    __shared__ float Bs[16][132];

    const int tid = threadIdx.x;
    const int tx  = tid & 15;
    const int ty  = tid >> 4;

    // A rows from g_h
    int rowm[2];
    const float* aptr[2];
    #pragma unroll
    for (int q = 0; q < 2; q++) {
        int idx = tid * 2 + q;
        int m   = idx >> 2;
        int gm  = m0 + m;
        int r   = base + min(gm, cnt - 1);
        rowm[q] = m;
        aptr[q] = g_h + (size_t)r * HID_ + (idx & 3) * 4;
    }
    // B: w2[e] is [HID, DIM] row-major; tile 16 x 128 = 512 f4, 2 per thread
    int  kB[2], nfB[2];
    const float* bptr[2];
    #pragma unroll
    for (int q = 0; q < 2; q++) {
        int idx = tid * 2 + q;
        kB[q]  = idx >> 5;
        nfB[q] = idx & 31;
        bptr[q] = w2 + ((size_t)e * HID_ + kB[q]) * DIM_ + n0 + nfB[q] * 4;
    }

    unsigned long long acc[8][4];
    #pragma unroll
    for (int i = 0; i < 8; i++)
        #pragma unroll
        for (int j = 0; j < 4; j++) acc[i][j] = 0ull;

    for (int k0 = 0; k0 < HID_; k0 += 16) {
        #pragma unroll
        for (int q = 0; q < 2; q++) {
            float4 v = *(const float4*)(aptr[q] + k0);
            int kq = ((tid * 2 + q) & 3) * 4;
            As[kq + 0][rowm[q]] = v.x;
            As[kq + 1][rowm[q]] = v.y;
            As[kq + 2][rowm[q]] = v.z;
            As[kq + 3][rowm[q]] = v.w;
        }
        #pragma unroll
        for (int q = 0; q < 2; q++) {
            float4 v = *(const float4*)(bptr[q] + (size_t)k0 * DIM_);
            *(float4*)&Bs[kB[q]][nfB[q] * 4] = v;
        }
        __syncthreads();
        #pragma unroll
        for (int k = 0; k < 16; k++) {
            float4 a0 = *(const float4*)&As[k][ty * 8];
            float4 a1 = *(const float4*)&As[k][ty * 8 + 4];
            ulonglong2 b0 = *(const ulonglong2*)&Bs[k][tx * 8];
            ulonglong2 b1 = *(const ulonglong2*)&Bs[k][tx * 8 + 4];
            float a[8] = {a0.x, a0.y, a0.z, a0.w, a1.x, a1.y, a1.z, a1.w};
            #pragma unroll
            for (int i = 0; i < 8; i++) {
                unsigned long long ad = pk2(a[i], a[i]);
                fma2(acc[i][0], ad, b0.x);
                fma2(acc[i][1], ad, b0.y);
                fma2(acc[i][2], ad, b1.x);
                fma2(acc[i][3], ad, b1.y);
            }
        }
        __syncthreads();
    }

    #pragma unroll
    for (int i = 0; i < 8; i++) {
        int gm = m0 + ty * 8 + i;
        if (gm < cnt) {
            float f0, f1, f2, f3, f4v, f5, f6, f7;
            upk2(acc[i][0], f0, f1);  upk2(acc[i][1], f2, f3);
            upk2(acc[i][2], f4v, f5); upk2(acc[i][3], f6, f7);
            float* yp = &g_y[(size_t)(base + gm) * DIM_ + n0 + tx * 8];
            *(float4*)(yp)     = make_float4(f0, f1, f2, f3);
            *(float4*)(yp + 4) = make_float4(f4v, f5, f6, f7);
        }
    }
}

// ---------------------------------------------------------------------------
// Kernel 5: weighted combine of a token's two expert outputs.
// ---------------------------------------------------------------------------
__global__ void combine_kernel(float* __restrict__ out) {
    const int t  = blockIdx.x;
    const int e0 = g_eid[t][0];
    const int e1 = g_eid[t][1];
    const int n0 = g_off[e0] + g_pos[t][0];
    const int n1 = g_off[e1] + g_pos[t][1];
    const float w0 = g_ew[t][0];
    const float w1 = g_ew[t][1];

    const float* y0 = &g_y[(size_t)n0 * DIM_];
    const float* y1 = &g_y[(size_t)n1 * DIM_];
    float*       op = out + (size_t)t * DIM_;

    for (int d = threadIdx.x * 4; d < DIM_; d += blockDim.x * 4) {
        float4 a = *(const float4*)(y0 + d);
        float4 b = *(const float4*)(y1 + d);
        float4 o;
        o.x = w0 * a.x + w1 * b.x;
        o.y = w0 * a.y + w1 * b.y;
        o.z = w0 * a.z + w1 * b.z;
        o.w = w0 * a.w + w1 * b.w;
        *(float4*)(op + d) = o;
    }
}

// ---------------------------------------------------------------------------
// Entry point
// ---------------------------------------------------------------------------
extern "C" void kernel_launch(void* const* d_in, const int* in_sizes, int n_in,
                              void* d_out, int out_size) {
    const float* x  = (const float*)d_in[0];
    const float* gw = (const float*)d_in[1];
    const float* w1 = (const float*)d_in[2];
    const float* w2 = (const float*)d_in[3];
    const float* w3 = (const float*)d_in[4];
    float* out = (float*)d_out;

    gate_kernel<<<T_TOKENS, 256>>>(x, gw);
    route_kernel<<<1, 256>>>();
    ffn1_kernel<<<dim3(HID_ / 64, T_TOKENS / 128, NEXP), 256>>>(x, w1, w3);
    ffn2_kernel<<<dim3(DIM_ / 128, T_TOKENS / 128, NEXP), 256>>>(w2);
    combine_kernel<<<T_TOKENS, 256>>>(out);
}

// round 2
// speedup vs baseline: 1.0525x; 1.0525x over previous
#include <cuda_runtime.h>
#include <cstdint>

// Problem constants
#define T_TOKENS 2048
#define DIM_     2048
#define HID_     5632
#define NEXP     8
#define NENT     (T_TOKENS * 2)   // total (token, expert) assignments: top-2

// ---------------------------------------------------------------------------
// Scratch (device globals — no cudaMalloc allowed)
// ---------------------------------------------------------------------------
__device__ int   g_eid [T_TOKENS][2];   // top-2 expert ids per token
__device__ float g_ew  [T_TOKENS][2];   // softmaxed combine weights
__device__ int   g_pos [T_TOKENS][2];   // position of token within its expert's list
__device__ int   g_list[NEXP][T_TOKENS];// token ids per expert (compact)
__device__ int   g_cnt [NEXP];
__device__ int   g_off [NEXP];          // exclusive prefix of counts -> entry base
__device__ float g_h   [(size_t)NENT * HID_];  // 92 MB: SwiGLU hidden per entry
__device__ float g_y   [(size_t)NENT * DIM_];  // 33 MB: per-entry FFN output

// ---------------------------------------------------------------------------
// f32x2 packed-FMA helpers (fma.rn.f32x2 doubles fp32 FMA throughput on sm_103a)
// ---------------------------------------------------------------------------
__device__ __forceinline__ unsigned long long pk2(float lo, float hi) {
    unsigned long long r;
    asm("mov.b64 %0, {%1, %2};" : "=l"(r)
        : "r"(__float_as_uint(lo)), "r"(__float_as_uint(hi)));
    return r;
}
__device__ __forceinline__ void upk2(unsigned long long v, float& lo, float& hi) {
    unsigned a, b;
    asm("mov.b64 {%0, %1}, %2;" : "=r"(a), "=r"(b) : "l"(v));
    lo = __uint_as_float(a);
    hi = __uint_as_float(b);
}
__device__ __forceinline__ void fma2(unsigned long long& acc,
                                     unsigned long long a, unsigned long long b) {
    asm("fma.rn.f32x2 %0, %1, %2, %0;" : "+l"(acc) : "l"(a), "l"(b));
}

// ---------------------------------------------------------------------------
// Kernel 1: gating scores + top-2 + softmax.  One block per token, 8 warps:
// warp w computes dot(x[t], gate_w[w]).
// ---------------------------------------------------------------------------
__global__ void gate_kernel(const float* __restrict__ x,
                            const float* __restrict__ gw) {
    const int t    = blockIdx.x;
    const int lane = threadIdx.x & 31;
    const int w    = threadIdx.x >> 5;

    const float* xr = x  + (size_t)t * DIM_;
    const float* gr = gw + (size_t)w * DIM_;

    float s = 0.f;
    for (int d = lane * 4; d < DIM_; d += 32 * 4) {
        float4 a = *(const float4*)(xr + d);
        float4 b = *(const float4*)(gr + d);
        s += a.x * b.x + a.y * b.y + a.z * b.z + a.w * b.w;
    }
    #pragma unroll
    for (int o = 16; o; o >>= 1) s += __shfl_xor_sync(0xffffffffu, s, o);

    __shared__ float sc[NEXP];
    if (lane == 0) sc[w] = s;
    __syncthreads();

    if (threadIdx.x == 0) {
        // top-1 (lowest index wins ties, matching jax top_k)
        int b0 = 0; float s0 = sc[0];
        #pragma unroll
        for (int e = 1; e < NEXP; e++) if (sc[e] > s0) { s0 = sc[e]; b0 = e; }
        // top-2
        int b1 = -1; float s1 = -1e30f;
        #pragma unroll
        for (int e = 0; e < NEXP; e++)
            if (e != b0 && sc[e] > s1) { s1 = sc[e]; b1 = e; }
        // softmax over [s0, s1] (s0 >= s1)
        float e1  = __expf(s1 - s0);
        float inv = 1.f / (1.f + e1);
        g_eid[t][0] = b0; g_eid[t][1] = b1;
        g_ew [t][0] = inv; g_ew [t][1] = e1 * inv;
    }
}

// ---------------------------------------------------------------------------
// Kernel 2: build deterministic per-expert token lists (warp-scan, no atomics).
// One block, warp e scans all tokens in order for expert e.
// ---------------------------------------------------------------------------
__global__ void route_kernel() {
    const int lane = threadIdx.x & 31;
    const int e    = threadIdx.x >> 5;
    if (e < NEXP) {
        int cnt = 0;
        for (int t0 = 0; t0 < T_TOKENS; t0 += 32) {
            int  t   = t0 + lane;
            int  e0  = g_eid[t][0];
            int  e1  = g_eid[t][1];
            bool sel = (e0 == e) || (e1 == e);
            int  slot = (e0 == e) ? 0 : 1;
            unsigned m = __ballot_sync(0xffffffffu, sel);
            if (sel) {
                int p = cnt + __popc(m & ((1u << lane) - 1u));
                g_list[e][p]   = t;
                g_pos[t][slot] = p;
            }
            cnt += __popc(m);
        }
        if (lane == 0) g_cnt[e] = cnt;
    }
    __syncthreads();
    if (threadIdx.x == 0) {
        int off = 0;
        #pragma unroll
        for (int i = 0; i < NEXP; i++) { g_off[i] = off; off += g_cnt[i]; }
    }
}

// ---------------------------------------------------------------------------
// Kernel 3: grouped GEMM1, fused:  h = silu(x @ w1[e]) * (x @ w3[e])
// Tile: 128 tokens x 64 hidden cols, computing both w1 and w3 contributions
// (128 effective B columns).  256 threads, 8x(4+4) microtile, f32x2 FMAs.
// ---------------------------------------------------------------------------
__global__ __launch_bounds__(256, 2)
void ffn1_kernel(const float* __restrict__ x,
                 const float* __restrict__ w1,
                 const float* __restrict__ w3) {
    const int e   = blockIdx.z;
    const int cnt = g_cnt[e];
    const int m0  = blockIdx.y * 128;
    if (m0 >= cnt) return;
    const int n0   = blockIdx.x * 64;
    const int base = g_off[e];

    __shared__ float As[16][132];   // [k][m], padded
    __shared__ float Bs[16][132];   // [k][0..63]=w1 cols, [64..127]=w3 cols

    const int tid = threadIdx.x;
    const int tx  = tid & 15;
    const int ty  = tid >> 4;

    // A-load mapping: 512 float4 = 128 rows x 4 quads; 2 per thread
    int rowm[2];
    const float* aptr[2];
    #pragma unroll
    for (int q = 0; q < 2; q++) {
        int idx = tid * 2 + q;
        int m   = idx >> 2;
        int gm  = m0 + m;
        int tk  = g_list[e][min(gm, cnt - 1)];
        rowm[q] = m;
        aptr[q] = x + (size_t)tk * DIM_ + (idx & 3) * 4;
    }
    // B-load mapping: 16 k-rows x 16 float4 per matrix; 1 f4 from each of w1,w3
    const int kb = tid >> 4;
    const int nf = tid & 15;
    const float* b1p = w1 + ((size_t)e * DIM_ + kb) * HID_ + n0 + nf * 4;
    const float* b3p = w3 + ((size_t)e * DIM_ + kb) * HID_ + n0 + nf * 4;

    unsigned long long au[8][2], av[8][2];
    #pragma unroll
    for (int i = 0; i < 8; i++) { au[i][0] = au[i][1] = av[i][0] = av[i][1] = 0ull; }

    for (int k0 = 0; k0 < DIM_; k0 += 16) {
        #pragma unroll
        for (int q = 0; q < 2; q++) {
            float4 v = *(const float4*)(aptr[q] + k0);
            int kq = ((tid * 2 + q) & 3) * 4;
            As[kq + 0][rowm[q]] = v.x;
            As[kq + 1][rowm[q]] = v.y;
            As[kq + 2][rowm[q]] = v.z;
            As[kq + 3][rowm[q]] = v.w;
        }
        {
            float4 v1 = *(const float4*)(b1p + (size_t)k0 * HID_);
            float4 v3 = *(const float4*)(b3p + (size_t)k0 * HID_);
            *(float4*)&Bs[kb][nf * 4]      = v1;
            *(float4*)&Bs[kb][64 + nf * 4] = v3;
        }
        __syncthreads();
        #pragma unroll
        for (int k = 0; k < 16; k++) {
            float4 a0 = *(const float4*)&As[k][ty * 8];
            float4 a1 = *(const float4*)&As[k][ty * 8 + 4];
            ulonglong2 bu = *(const ulonglong2*)&Bs[k][tx * 4];
            ulonglong2 bv = *(const ulonglong2*)&Bs[k][64 + tx * 4];
            float a[8] = {a0.x, a0.y, a0.z, a0.w, a1.x, a1.y, a1.z, a1.w};
            #pragma unroll
            for (int i = 0; i < 8; i++) {
                unsigned long long ad = pk2(a[i], a[i]);
                fma2(au[i][0], ad, bu.x);
                fma2(au[i][1], ad, bu.y);
                fma2(av[i][0], ad, bv.x);
                fma2(av[i][1], ad, bv.y);
            }
        }
        __syncthreads();
    }

    // epilogue: h = silu(u) * v
    #pragma unroll
    for (int i = 0; i < 8; i++) {
        int gm = m0 + ty * 8 + i;
        if (gm < cnt) {
            float u0, u1, u2, u3, v0, v1, v2, v3;
            upk2(au[i][0], u0, u1); upk2(au[i][1], u2, u3);
            upk2(av[i][0], v0, v1); upk2(av[i][1], v2, v3);
            float4 hv;
            hv.x = u0 / (1.f + __expf(-u0)) * v0;
            hv.y = u1 / (1.f + __expf(-u1)) * v1;
            hv.z = u2 / (1.f + __expf(-u2)) * v2;
            hv.w = u3 / (1.f + __expf(-u3)) * v3;
            *(float4*)&g_h[(size_t)(base + gm) * HID_ + n0 + tx * 4] = hv;
        }
    }
}

// ---------------------------------------------------------------------------
// Kernel 4: grouped GEMM2:  y = h @ w2[e]   (weights applied later in combine)
// Tile: 128 entries x 128 out cols, K=HID.  256 threads, 8x8, f32x2.
// ---------------------------------------------------------------------------
__global__ __launch_bounds__(256, 2)
void ffn2_kernel(const float* __restrict__ w2) {
    const int e   = blockIdx.z;
    const int cnt = g_cnt[e];
    const int m0  = blockIdx.y * 128;
    if (m0 >= cnt) return;
    const int n0   = blockIdx.x * 128;
    const int base = g_off[e];

    __shared__ float As[16][132];
    __shared__ float Bs[16][132];

    const int tid = threadIdx.x;
    const int tx  = tid & 15;
    const int ty  = tid >> 4;

    // A rows from g_h
    int rowm[2];
    const float* aptr[2];
    #pragma unroll
    for (int q = 0; q < 2; q++) {
        int idx = tid * 2 + q;
        int m   = idx >> 2;
        int gm  = m0 + m;
        int r   = base + min(gm, cnt - 1);
        rowm[q] = m;
        aptr[q] = g_h + (size_t)r * HID_ + (idx & 3) * 4;
    }
    // B: w2[e] is [HID, DIM] row-major; tile 16 x 128 = 512 f4, 2 per thread
    int  kB[2], nfB[2];
    const float* bptr[2];
    #pragma unroll
    for (int q = 0; q < 2; q++) {
        int idx = tid * 2 + q;
        kB[q]  = idx >> 5;
        nfB[q] = idx & 31;
        bptr[q] = w2 + ((size_t)e * HID_ + kB[q]) * DIM_ + n0 + nfB[q] * 4;
    }

    unsigned long long acc[8][4];
    #pragma unroll
    for (int i = 0; i < 8; i++)
        #pragma unroll
        for (int j = 0; j < 4; j++) acc[i][j] = 0ull;

    for (int k0 = 0; k0 < HID_; k0 += 16) {
        #pragma unroll
        for (int q = 0; q < 2; q++) {
            float4 v = *(const float4*)(aptr[q] + k0);
            int kq = ((tid * 2 + q) & 3) * 4;
            As[kq + 0][rowm[q]] = v.x;
            As[kq + 1][rowm[q]] = v.y;
            As[kq + 2][rowm[q]] = v.z;
            As[kq + 3][rowm[q]] = v.w;
        }
        #pragma unroll
        for (int q = 0; q < 2; q++) {
            float4 v = *(const float4*)(bptr[q] + (size_t)k0 * DIM_);
            *(float4*)&Bs[kB[q]][nfB[q] * 4] = v;
        }
        __syncthreads();
        #pragma unroll
        for (int k = 0; k < 16; k++) {
            float4 a0 = *(const float4*)&As[k][ty * 8];
            float4 a1 = *(const float4*)&As[k][ty * 8 + 4];
            ulonglong2 b0 = *(const ulonglong2*)&Bs[k][tx * 8];
            ulonglong2 b1 = *(const ulonglong2*)&Bs[k][tx * 8 + 4];
            float a[8] = {a0.x, a0.y, a0.z, a0.w, a1.x, a1.y, a1.z, a1.w};
            #pragma unroll
            for (int i = 0; i < 8; i++) {
                unsigned long long ad = pk2(a[i], a[i]);
                fma2(acc[i][0], ad, b0.x);
                fma2(acc[i][1], ad, b0.y);
                fma2(acc[i][2], ad, b1.x);
                fma2(acc[i][3], ad, b1.y);
            }
        }
        __syncthreads();
    }

    #pragma unroll
    for (int i = 0; i < 8; i++) {
        int gm = m0 + ty * 8 + i;
        if (gm < cnt) {
            float f0, f1, f2, f3, f4v, f5, f6, f7;
            upk2(acc[i][0], f0, f1);  upk2(acc[i][1], f2, f3);
            upk2(acc[i][2], f4v, f5); upk2(acc[i][3], f6, f7);
            float* yp = &g_y[(size_t)(base + gm) * DIM_ + n0 + tx * 8];
            *(float4*)(yp)     = make_float4(f0, f1, f2, f3);
            *(float4*)(yp + 4) = make_float4(f4v, f5, f6, f7);
        }
    }
}

// ---------------------------------------------------------------------------
// Kernel 5: weighted combine of a token's two expert outputs.
// ---------------------------------------------------------------------------
__global__ void combine_kernel(float* __restrict__ out) {
    const int t  = blockIdx.x;
    const int e0 = g_eid[t][0];
    const int e1 = g_eid[t][1];
    const int n0 = g_off[e0] + g_pos[t][0];
    const int n1 = g_off[e1] + g_pos[t][1];
    const float w0 = g_ew[t][0];
    const float w1 = g_ew[t][1];

    const float* y0 = &g_y[(size_t)n0 * DIM_];
    const float* y1 = &g_y[(size_t)n1 * DIM_];
    float*       op = out + (size_t)t * DIM_;

    for (int d = threadIdx.x * 4; d < DIM_; d += blockDim.x * 4) {
        float4 a = *(const float4*)(y0 + d);
        float4 b = *(const float4*)(y1 + d);
        float4 o;
        o.x = w0 * a.x + w1 * b.x;
        o.y = w0 * a.y + w1 * b.y;
        o.z = w0 * a.z + w1 * b.z;
        o.w = w0 * a.w + w1 * b.w;
        *(float4*)(op + d) = o;
    }
}

// ---------------------------------------------------------------------------
// Entry point
// ---------------------------------------------------------------------------
extern "C" void kernel_launch(void* const* d_in, const int* in_sizes, int n_in,
                              void* d_out, int out_size) {
    const float* x  = (const float*)d_in[0];
    const float* gw = (const float*)d_in[1];
    const float* w1 = (const float*)d_in[2];
    const float* w2 = (const float*)d_in[3];
    const float* w3 = (const float*)d_in[4];
    float* out = (float*)d_out;

    gate_kernel<<<T_TOKENS, 256>>>(x, gw);
    route_kernel<<<1, 256>>>();
    ffn1_kernel<<<dim3(HID_ / 64, T_TOKENS / 128, NEXP), 256>>>(x, w1, w3);
    ffn2_kernel<<<dim3(DIM_ / 128, T_TOKENS / 128, NEXP), 256>>>(w2);
    combine_kernel<<<T_TOKENS, 256>>>(out);
}

// round 4
// speedup vs baseline: 2.0679x; 1.9648x over previous
#include <cuda_runtime.h>
#include <cuda_bf16.h>
#include <cstdint>

#define T_TOKENS 2048
#define DIM_     2048
#define HID_     5632
#define NEXP     8
#define NENT     (T_TOKENS * 2)

// ---------------------------------------------------------------------------
// Scratch (device globals — no cudaMalloc allowed)
// ---------------------------------------------------------------------------
__device__ int   g_eid [T_TOKENS][2];
__device__ float g_ew  [T_TOKENS][2];
__device__ int   g_pos [T_TOKENS][2];
__device__ int   g_list[NEXP][T_TOKENS];
__device__ int   g_cnt [NEXP];
__device__ int   g_off [NEXP];
__device__ __nv_bfloat16 g_xhi[(size_t)T_TOKENS * DIM_];
__device__ __nv_bfloat16 g_xlo[(size_t)T_TOKENS * DIM_];
__device__ __nv_bfloat16 g_hh [(size_t)NENT * HID_];
__device__ __nv_bfloat16 g_hl [(size_t)NENT * HID_];
__device__ float         g_y  [(size_t)NENT * DIM_];

// ---------------------------------------------------------------------------
// Helpers
// ---------------------------------------------------------------------------
__device__ __forceinline__ uint32_t smem_u32(const void* p) {
    uint32_t a;
    asm("{ .reg .u64 t; cvta.to.shared.u64 t, %1; cvt.u32.u64 %0, t; }" : "=r"(a) : "l"(p));
    return a;
}
__device__ __forceinline__ uint32_t pkbf(__nv_bfloat16 a, __nv_bfloat16 b) {
    return (uint32_t)__bfloat16_as_ushort(a) | ((uint32_t)__bfloat16_as_ushort(b) << 16);
}
__device__ __forceinline__ void split_pair(float f0, float f1, uint32_t& hp, uint32_t& lp) {
    __nv_bfloat16 h0 = __float2bfloat16(f0);
    __nv_bfloat16 h1 = __float2bfloat16(f1);
    __nv_bfloat16 l0 = __float2bfloat16(f0 - __bfloat162float(h0));
    __nv_bfloat16 l1 = __float2bfloat16(f1 - __bfloat162float(h1));
    hp = pkbf(h0, h1);
    lp = pkbf(l0, l1);
}

#define LDM_X4(r, addr)                                                          \
    asm volatile("ldmatrix.sync.aligned.m8n8.x4.shared.b16 {%0,%1,%2,%3}, [%4];" \
        : "=r"((r)[0]), "=r"((r)[1]), "=r"((r)[2]), "=r"((r)[3]) : "r"(addr))

#define MMA_BF16(d, a, b0, b1)                                                   \
    asm volatile("mma.sync.aligned.m16n8k16.row.col.f32.bf16.bf16.f32 "          \
        "{%0,%1,%2,%3}, {%4,%5,%6,%7}, {%8,%9}, {%0,%1,%2,%3};"                  \
        : "+f"((d)[0]), "+f"((d)[1]), "+f"((d)[2]), "+f"((d)[3])                 \
        : "r"((a)[0]), "r"((a)[1]), "r"((a)[2]), "r"((a)[3]), "r"(b0), "r"(b1))

// Smem tile geometry: rows of 32 bf16, padded to 80 bytes.
// Bank-quad of (row, kq) = (5*row + kq) mod 8 -> permutation per kq: LDSM conflict-free.
#define ROWB   80
#define TILE_B 10240            // 128 rows * 80B
#define STAGE_B (4 * TILE_B)    // Ah Al Bh Bl
#define SMEM_TOT (2 * STAGE_B)  // 81920

// ---------------------------------------------------------------------------
// Gating + routing + x split
// ---------------------------------------------------------------------------
__global__ void gate_kernel(const float* __restrict__ x, const float* __restrict__ gw) {
    const int t = blockIdx.x, lane = threadIdx.x & 31, w = threadIdx.x >> 5;
    const float* xr = x + (size_t)t * DIM_;
    const float* gr = gw + (size_t)w * DIM_;
    float s = 0.f;
    for (int d = lane * 4; d < DIM_; d += 128) {
        float4 a = *(const float4*)(xr + d);
        float4 b = *(const float4*)(gr + d);
        s += a.x * b.x + a.y * b.y + a.z * b.z + a.w * b.w;
    }
    #pragma unroll
    for (int o = 16; o; o >>= 1) s += __shfl_xor_sync(0xffffffffu, s, o);
    __shared__ float sc[NEXP];
    if (lane == 0) sc[w] = s;
    __syncthreads();
    if (threadIdx.x == 0) {
        int b0 = 0; float s0 = sc[0];
        #pragma unroll
        for (int e = 1; e < NEXP; e++) if (sc[e] > s0) { s0 = sc[e]; b0 = e; }
        int b1 = -1; float s1 = -1e30f;
        #pragma unroll
        for (int e = 0; e < NEXP; e++) if (e != b0 && sc[e] > s1) { s1 = sc[e]; b1 = e; }
        float e1 = __expf(s1 - s0);
        float inv = 1.f / (1.f + e1);
        g_eid[t][0] = b0; g_eid[t][1] = b1;
        g_ew [t][0] = inv; g_ew [t][1] = e1 * inv;
    }
}

__global__ void route_kernel() {
    const int lane = threadIdx.x & 31, e = threadIdx.x >> 5;
    if (e < NEXP) {
        int cnt = 0;
        for (int t0 = 0; t0 < T_TOKENS; t0 += 32) {
            int t = t0 + lane;
            int e0 = g_eid[t][0], e1 = g_eid[t][1];
            bool sel = (e0 == e) || (e1 == e);
            int slot = (e0 == e) ? 0 : 1;
            unsigned m = __ballot_sync(0xffffffffu, sel);
            if (sel) {
                int p = cnt + __popc(m & ((1u << lane) - 1u));
                g_list[e][p] = t;
                g_pos[t][slot] = p;
            }
            cnt += __popc(m);
        }
        if (lane == 0) g_cnt[e] = cnt;
    }
    __syncthreads();
    if (threadIdx.x == 0) {
        int off = 0;
        #pragma unroll
        for (int i = 0; i < NEXP; i++) { g_off[i] = off; off += g_cnt[i]; }
    }
}

__global__ void split_x_kernel(const float* __restrict__ x) {
    int i = blockIdx.x * blockDim.x + threadIdx.x;
    float4 v = ((const float4*)x)[i];
    size_t o = (size_t)i * 4;
    float vv[4] = {v.x, v.y, v.z, v.w};
    #pragma unroll
    for (int k = 0; k < 4; k++) {
        __nv_bfloat16 h = __float2bfloat16(vv[k]);
        g_xhi[o + k] = h;
        g_xlo[o + k] = __float2bfloat16(vv[k] - __bfloat162float(h));
    }
}

// ---------------------------------------------------------------------------
// GEMM1: u = x@w1, v = x@w3 (3-term bf16 split, mma.sync), h = silu(u)*v
// BM=128 tokens, 64 u-cols + 64 v-cols (B tile rows 0-63 = w1, 64-127 = w3),
// BK=32.  512 threads, warp grid 4(m) x 4(n), warp tile 32x32.
// ---------------------------------------------------------------------------
__global__ void __launch_bounds__(512, 1) ffn1_kernel(const float* __restrict__ w1,
                                                      const float* __restrict__ w3) {
    const int e   = blockIdx.z;
    const int cnt = g_cnt[e];
    const int m0  = blockIdx.x * 128;
    if (m0 >= cnt) return;
    const int n0   = blockIdx.y * 64;
    const int base = g_off[e];

    extern __shared__ char sm[];
    const uint32_t sbase = smem_u32(sm);
    const int tid = threadIdx.x, lane = tid & 31, wid = tid >> 5;
    const int wm = wid & 3, wn = wid >> 2;

    const float* w1e = w1 + (size_t)e * DIM_ * HID_;
    const float* w3e = w3 + (size_t)e * DIM_ * HID_;

    // A loader: 2 uint4/thread (Ah + Al tiles, 512 uint4 each)
    const __nv_bfloat16* apA[2];
    uint32_t aoA[2];
    #pragma unroll
    for (int q = 0; q < 2; q++) {
        int idx = tid + q * 512;
        int mat = idx >> 9;
        int rem = idx & 511;
        int row = rem >> 2, kq = rem & 3;
        int tok = g_list[e][min(m0 + row, cnt - 1)];
        apA[q] = (mat ? g_xlo : g_xhi) + (size_t)tok * DIM_ + kq * 8;
        aoA[q] = mat * TILE_B + row * ROWB + kq * 16;
    }
    // B loader: 1 task/thread: n-row (0..127), k-block (0..3)
    const int bn = tid & 127, bkb = tid >> 7;
    const float* pB = ((bn < 64) ? w1e : w3e) + (size_t)(bkb * 8) * HID_ + (n0 + (bn & 63));
    const uint32_t boH = 2 * TILE_B + bn * ROWB + bkb * 16;

    // ldmatrix per-lane address bases
    const int mi = lane >> 3, lr = lane & 7;
    const uint32_t aLB = (uint32_t)((wm * 32 + (mi & 1) * 8 + lr) * ROWB + (mi >> 1) * 16);
    const uint32_t bLB = (uint32_t)((wn * 32 + (mi >> 1) * 8 + lr) * ROWB + (mi & 1) * 16);

    float acc[2][4][4];
    #pragma unroll
    for (int a = 0; a < 2; a++)
        #pragma unroll
        for (int b = 0; b < 4; b++)
            #pragma unroll
            for (int c = 0; c < 4; c++) acc[a][b][c] = 0.f;

    uint4 pa[2];
    float pf[8];
    #pragma unroll
    for (int q = 0; q < 2; q++) pa[q] = *(const uint4*)(apA[q]);
    #pragma unroll
    for (int j = 0; j < 8; j++) pf[j] = pB[(size_t)j * HID_];

    const int NCH = DIM_ / 32;   // 64
    for (int i = 0; i < NCH; i++) {
        char* st = sm + (i & 1) * STAGE_B;
        const uint32_t stS = sbase + (i & 1) * STAGE_B;
        #pragma unroll
        for (int q = 0; q < 2; q++) *(uint4*)(st + aoA[q]) = pa[q];
        {
            uint32_t hp[4], lp[4];
            #pragma unroll
            for (int j = 0; j < 4; j++) split_pair(pf[2*j], pf[2*j+1], hp[j], lp[j]);
            *(uint4*)(st + boH)          = make_uint4(hp[0], hp[1], hp[2], hp[3]);
            *(uint4*)(st + boH + TILE_B) = make_uint4(lp[0], lp[1], lp[2], lp[3]);
        }
        if (i + 1 < NCH) {
            int k0n = (i + 1) * 32;
            #pragma unroll
            for (int q = 0; q < 2; q++) pa[q] = *(const uint4*)(apA[q] + k0n);
            #pragma unroll
            for (int j = 0; j < 8; j++) pf[j] = pB[(size_t)(k0n + j) * HID_];
        }
        __syncthreads();
        #pragma unroll
        for (int ks = 0; ks < 2; ks++) {
            uint32_t ah[2][4], al[2][4], bh[2][4], bl[2][4];
            #pragma unroll
            for (int mt = 0; mt < 2; mt++) {
                LDM_X4(ah[mt], stS + aLB + mt * (16 * ROWB) + ks * 32);
                LDM_X4(al[mt], stS + TILE_B + aLB + mt * (16 * ROWB) + ks * 32);
            }
            #pragma unroll
            for (int ng = 0; ng < 2; ng++) {
                LDM_X4(bh[ng], stS + 2 * TILE_B + bLB + ng * (16 * ROWB) + ks * 32);
                LDM_X4(bl[ng], stS + 3 * TILE_B + bLB + ng * (16 * ROWB) + ks * 32);
            }
            #pragma unroll
            for (int mt = 0; mt < 2; mt++)
                #pragma unroll
                for (int ng = 0; ng < 2; ng++)
                    #pragma unroll
                    for (int h2 = 0; h2 < 2; h2++) {
                        int nt = ng * 2 + h2;
                        MMA_BF16(acc[mt][nt], ah[mt], bh[ng][2*h2], bh[ng][2*h2+1]);
                        MMA_BF16(acc[mt][nt], al[mt], bh[ng][2*h2], bh[ng][2*h2+1]);
                        MMA_BF16(acc[mt][nt], ah[mt], bl[ng][2*h2], bl[ng][2*h2+1]);
                    }
        }
        __syncthreads();
    }

    // epilogue: v-warps (wn>=2) publish v via smem, u-warps fuse SwiGLU
    float* vb = (float*)sm;   // [128][68] f32
    if (wn >= 2) {
        #pragma unroll
        for (int mt = 0; mt < 2; mt++)
            #pragma unroll
            for (int nt = 0; nt < 4; nt++) {
                int r = wm * 32 + mt * 16 + (lane >> 2);
                int c = (wn - 2) * 32 + nt * 8 + (lane & 3) * 2;
                vb[r * 68 + c]            = acc[mt][nt][0];
                vb[r * 68 + c + 1]        = acc[mt][nt][1];
                vb[(r + 8) * 68 + c]      = acc[mt][nt][2];
                vb[(r + 8) * 68 + c + 1]  = acc[mt][nt][3];
            }
    }
    __syncthreads();
    if (wn < 2) {
        #pragma unroll
        for (int mt = 0; mt < 2; mt++)
            #pragma unroll
            for (int nt = 0; nt < 4; nt++) {
                int c = wn * 32 + nt * 8 + (lane & 3) * 2;
                #pragma unroll
                for (int rr = 0; rr < 2; rr++) {
                    int r  = wm * 32 + mt * 16 + (lane >> 2) + rr * 8;
                    int gm = m0 + r;
                    float u0 = acc[mt][nt][2*rr], u1 = acc[mt][nt][2*rr+1];
                    float v0 = vb[r * 68 + c], v1 = vb[r * 68 + c + 1];
                    float h0 = u0 / (1.f + __expf(-u0)) * v0;
                    float h1 = u1 / (1.f + __expf(-u1)) * v1;
                    uint32_t hp, lp;
                    split_pair(h0, h1, hp, lp);
                    if (gm < cnt) {
                        size_t dst = (size_t)(base + gm) * HID_ + n0 + c;
                        *(uint32_t*)(g_hh + dst) = hp;
                        *(uint32_t*)(g_hl + dst) = lp;
                    }
                }
            }
    }
}

// ---------------------------------------------------------------------------
// GEMM2: y = h @ w2 (3-term split).  BM=128, BN=128, BK=32.
// ---------------------------------------------------------------------------
__global__ void __launch_bounds__(512, 1) ffn2_kernel(const float* __restrict__ w2) {
    const int e   = blockIdx.z;
    const int cnt = g_cnt[e];
    const int m0  = blockIdx.x * 128;
    if (m0 >= cnt) return;
    const int n0   = blockIdx.y * 128;
    const int base = g_off[e];

    extern __shared__ char sm[];
    const uint32_t sbase = smem_u32(sm);
    const int tid = threadIdx.x, lane = tid & 31, wid = tid >> 5;
    const int wm = wid & 3, wn = wid >> 2;

    const float* w2e = w2 + (size_t)e * HID_ * DIM_;

    const __nv_bfloat16* apA[2];
    uint32_t aoA[2];
    #pragma unroll
    for (int q = 0; q < 2; q++) {
        int idx = tid + q * 512;
        int mat = idx >> 9;
        int rem = idx & 511;
        int row = rem >> 2, kq = rem & 3;
        int r   = base + min(m0 + row, cnt - 1);
        apA[q] = (mat ? g_hl : g_hh) + (size_t)r * HID_ + kq * 8;
        aoA[q] = mat * TILE_B + row * ROWB + kq * 16;
    }
    const int bn = tid & 127, bkb = tid >> 7;
    const float* pB = w2e + (size_t)(bkb * 8) * DIM_ + (n0 + bn);
    const uint32_t boH = 2 * TILE_B + bn * ROWB + bkb * 16;

    const int mi = lane >> 3, lr = lane & 7;
    const uint32_t aLB = (uint32_t)((wm * 32 + (mi & 1) * 8 + lr) * ROWB + (mi >> 1) * 16);
    const uint32_t bLB = (uint32_t)((wn * 32 + (mi >> 1) * 8 + lr) * ROWB + (mi & 1) * 16);

    float acc[2][4][4];
    #pragma unroll
    for (int a = 0; a < 2; a++)
        #pragma unroll
        for (int b = 0; b < 4; b++)
            #pragma unroll
            for (int c = 0; c < 4; c++) acc[a][b][c] = 0.f;

    uint4 pa[2];
    float pf[8];
    #pragma unroll
    for (int q = 0; q < 2; q++) pa[q] = *(const uint4*)(apA[q]);
    #pragma unroll
    for (int j = 0; j < 8; j++) pf[j] = pB[(size_t)j * DIM_];

    const int NCH = HID_ / 32;   // 176
    for (int i = 0; i < NCH; i++) {
        char* st = sm + (i & 1) * STAGE_B;
        const uint32_t stS = sbase + (i & 1) * STAGE_B;
        #pragma unroll
        for (int q = 0; q < 2; q++) *(uint4*)(st + aoA[q]) = pa[q];
        {
            uint32_t hp[4], lp[4];
            #pragma unroll
            for (int j = 0; j < 4; j++) split_pair(pf[2*j], pf[2*j+1], hp[j], lp[j]);
            *(uint4*)(st + boH)          = make_uint4(hp[0], hp[1], hp[2], hp[3]);
            *(uint4*)(st + boH + TILE_B) = make_uint4(lp[0], lp[1], lp[2], lp[3]);
        }
        if (i + 1 < NCH) {
            int k0n = (i + 1) * 32;
            #pragma unroll
            for (int q = 0; q < 2; q++) pa[q] = *(const uint4*)(apA[q] + k0n);
            #pragma unroll
            for (int j = 0; j < 8; j++) pf[j] = pB[(size_t)(k0n + j) * DIM_];
        }
        __syncthreads();
        #pragma unroll
        for (int ks = 0; ks < 2; ks++) {
            uint32_t ah[2][4], al[2][4], bh[2][4], bl[2][4];
            #pragma unroll
            for (int mt = 0; mt < 2; mt++) {
                LDM_X4(ah[mt], stS + aLB + mt * (16 * ROWB) + ks * 32);
                LDM_X4(al[mt], stS + TILE_B + aLB + mt * (16 * ROWB) + ks * 32);
            }
            #pragma unroll
            for (int ng = 0; ng < 2; ng++) {
                LDM_X4(bh[ng], stS + 2 * TILE_B + bLB + ng * (16 * ROWB) + ks * 32);
                LDM_X4(bl[ng], stS + 3 * TILE_B + bLB + ng * (16 * ROWB) + ks * 32);
            }
            #pragma unroll
            for (int mt = 0; mt < 2; mt++)
                #pragma unroll
                for (int ng = 0; ng < 2; ng++)
                    #pragma unroll
                    for (int h2 = 0; h2 < 2; h2++) {
                        int nt = ng * 2 + h2;
                        MMA_BF16(acc[mt][nt], ah[mt], bh[ng][2*h2], bh[ng][2*h2+1]);
                        MMA_BF16(acc[mt][nt], al[mt], bh[ng][2*h2], bh[ng][2*h2+1]);
                        MMA_BF16(acc[mt][nt], ah[mt], bl[ng][2*h2], bl[ng][2*h2+1]);
                    }
        }
        __syncthreads();
    }

    #pragma unroll
    for (int mt = 0; mt < 2; mt++)
        #pragma unroll
        for (int nt = 0; nt < 4; nt++) {
            int c = wn * 32 + nt * 8 + (lane & 3) * 2;
            #pragma unroll
            for (int rr = 0; rr < 2; rr++) {
                int r  = wm * 32 + mt * 16 + (lane >> 2) + rr * 8;
                int gm = m0 + r;
                if (gm < cnt) {
                    size_t dst = (size_t)(base + gm) * DIM_ + n0 + c;
                    *(float2*)(g_y + dst) = make_float2(acc[mt][nt][2*rr], acc[mt][nt][2*rr+1]);
                }
            }
        }
}

// ---------------------------------------------------------------------------
// Combine
// ---------------------------------------------------------------------------
__global__ void combine_kernel(float* __restrict__ out) {
    const int t  = blockIdx.x;
    const int e0 = g_eid[t][0];
    const int e1 = g_eid[t][1];
    const int n0 = g_off[e0] + g_pos[t][0];
    const int n1 = g_off[e1] + g_pos[t][1];
    const float w0 = g_ew[t][0];
    const float w1 = g_ew[t][1];
    const float* y0 = &g_y[(size_t)n0 * DIM_];
    const float* y1 = &g_y[(size_t)n1 * DIM_];
    float* op = out + (size_t)t * DIM_;
    for (int d = threadIdx.x * 4; d < DIM_; d += blockDim.x * 4) {
        float4 a = *(const float4*)(y0 + d);
        float4 b = *(const float4*)(y1 + d);
        *(float4*)(op + d) = make_float4(w0 * a.x + w1 * b.x, w0 * a.y + w1 * b.y,
                                         w0 * a.z + w1 * b.z, w0 * a.w + w1 * b.w);
    }
}

// ---------------------------------------------------------------------------
// Entry point
// ---------------------------------------------------------------------------
extern "C" void kernel_launch(void* const* d_in, const int* in_sizes, int n_in,
                              void* d_out, int out_size) {
    const float* x  = (const float*)d_in[0];
    const float* gw = (const float*)d_in[1];
    const float* w1 = (const float*)d_in[2];
    const float* w2 = (const float*)d_in[3];
    const float* w3 = (const float*)d_in[4];
    float* out = (float*)d_out;

    cudaFuncSetAttribute(ffn1_kernel, cudaFuncAttributeMaxDynamicSharedMemorySize, SMEM_TOT);
    cudaFuncSetAttribute(ffn2_kernel, cudaFuncAttributeMaxDynamicSharedMemorySize, SMEM_TOT);

    gate_kernel<<<T_TOKENS, 256>>>(x, gw);
    route_kernel<<<1, 256>>>();
    split_x_kernel<<<(T_TOKENS * DIM_ / 4) / 256, 256>>>(x);
    ffn1_kernel<<<dim3(T_TOKENS / 128, HID_ / 64, NEXP), 512, SMEM_TOT>>>(w1, w3);
    ffn2_kernel<<<dim3(T_TOKENS / 128, DIM_ / 128, NEXP), 512, SMEM_TOT>>>(w2);
    combine_kernel<<<T_TOKENS, 256>>>(out);
}

// round 5
// speedup vs baseline: 2.2808x; 1.1030x over previous
#include <cuda_runtime.h>
#include <cuda_bf16.h>
#include <cstdint>

#define T_TOKENS 2048
#define DIM_     2048
#define HID_     5632
#define NEXP     8
#define NENT     (T_TOKENS * 2)

// ---------------------------------------------------------------------------
// Scratch (device globals — no cudaMalloc allowed)
// ---------------------------------------------------------------------------
__device__ int   g_eid [T_TOKENS][2];
__device__ float g_ew  [T_TOKENS][2];
__device__ int   g_pos [T_TOKENS][2];
__device__ int   g_list[NEXP][T_TOKENS];
__device__ int   g_cnt [NEXP];
__device__ int   g_off [NEXP];
__device__ __nv_bfloat16 g_xhi[(size_t)T_TOKENS * DIM_];
__device__ __nv_bfloat16 g_xlo[(size_t)T_TOKENS * DIM_];
__device__ __nv_bfloat16 g_hh [(size_t)NENT * HID_];
__device__ __nv_bfloat16 g_hl [(size_t)NENT * HID_];
__device__ float         g_y  [(size_t)NENT * DIM_];

// ---------------------------------------------------------------------------
// Helpers
// ---------------------------------------------------------------------------
__device__ __forceinline__ uint32_t smem_u32(const void* p) {
    uint32_t a;
    asm("{ .reg .u64 t; cvta.to.shared.u64 t, %1; cvt.u32.u64 %0, t; }" : "=r"(a) : "l"(p));
    return a;
}
__device__ __forceinline__ uint32_t pkbf(__nv_bfloat16 a, __nv_bfloat16 b) {
    return (uint32_t)__bfloat16_as_ushort(a) | ((uint32_t)__bfloat16_as_ushort(b) << 16);
}
__device__ __forceinline__ void split_pair(float f0, float f1, uint32_t& hp, uint32_t& lp) {
    __nv_bfloat16 h0 = __float2bfloat16(f0);
    __nv_bfloat16 h1 = __float2bfloat16(f1);
    __nv_bfloat16 l0 = __float2bfloat16(f0 - __bfloat162float(h0));
    __nv_bfloat16 l1 = __float2bfloat16(f1 - __bfloat162float(h1));
    hp = pkbf(h0, h1);
    lp = pkbf(l0, l1);
}

#define LDM_X4(r, addr)                                                          \
    asm volatile("ldmatrix.sync.aligned.m8n8.x4.shared.b16 {%0,%1,%2,%3}, [%4];" \
        : "=r"((r)[0]), "=r"((r)[1]), "=r"((r)[2]), "=r"((r)[3]) : "r"(addr))

#define MMA_BF16(d, a, b0, b1)                                                   \
    asm volatile("mma.sync.aligned.m16n8k16.row.col.f32.bf16.bf16.f32 "          \
        "{%0,%1,%2,%3}, {%4,%5,%6,%7}, {%8,%9}, {%0,%1,%2,%3};"                  \
        : "+f"((d)[0]), "+f"((d)[1]), "+f"((d)[2]), "+f"((d)[3])                 \
        : "r"((a)[0]), "r"((a)[1]), "r"((a)[2]), "r"((a)[3]), "r"(b0), "r"(b1))

// Smem geometry: rows of 32 bf16 padded to 80B -> conflict-free ldmatrix.
#define ROWB    80
#define TILE_A  10240           // 128 rows * 80B (one A matrix: hi or lo)
#define TILE_Bm 5120            // 64 rows * 80B (one B matrix)
#define OFF_AH  0
#define OFF_AL  10240
#define OFF_BH  20480
#define OFF_BL  25600
#define STAGE_B 30720
#define SMEM_TOT (2 * STAGE_B)  // 61440 -> 2 CTAs/SM

// ---------------------------------------------------------------------------
// Gating + routing + x split
// ---------------------------------------------------------------------------
__global__ void gate_kernel(const float* __restrict__ x, const float* __restrict__ gw) {
    const int t = blockIdx.x, lane = threadIdx.x & 31, w = threadIdx.x >> 5;
    const float* xr = x + (size_t)t * DIM_;
    const float* gr = gw + (size_t)w * DIM_;
    float s = 0.f;
    for (int d = lane * 4; d < DIM_; d += 128) {
        float4 a = *(const float4*)(xr + d);
        float4 b = *(const float4*)(gr + d);
        s += a.x * b.x + a.y * b.y + a.z * b.z + a.w * b.w;
    }
    #pragma unroll
    for (int o = 16; o; o >>= 1) s += __shfl_xor_sync(0xffffffffu, s, o);
    __shared__ float sc[NEXP];
    if (lane == 0) sc[w] = s;
    __syncthreads();
    if (threadIdx.x == 0) {
        int b0 = 0; float s0 = sc[0];
        #pragma unroll
        for (int e = 1; e < NEXP; e++) if (sc[e] > s0) { s0 = sc[e]; b0 = e; }
        int b1 = -1; float s1 = -1e30f;
        #pragma unroll
        for (int e = 0; e < NEXP; e++) if (e != b0 && sc[e] > s1) { s1 = sc[e]; b1 = e; }
        float e1 = __expf(s1 - s0);
        float inv = 1.f / (1.f + e1);
        g_eid[t][0] = b0; g_eid[t][1] = b1;
        g_ew [t][0] = inv; g_ew [t][1] = e1 * inv;
    }
}

__global__ void route_kernel() {
    const int lane = threadIdx.x & 31, e = threadIdx.x >> 5;
    if (e < NEXP) {
        int cnt = 0;
        for (int t0 = 0; t0 < T_TOKENS; t0 += 32) {
            int t = t0 + lane;
            int e0 = g_eid[t][0], e1 = g_eid[t][1];
            bool sel = (e0 == e) || (e1 == e);
            int slot = (e0 == e) ? 0 : 1;
            unsigned m = __ballot_sync(0xffffffffu, sel);
            if (sel) {
                int p = cnt + __popc(m & ((1u << lane) - 1u));
                g_list[e][p] = t;
                g_pos[t][slot] = p;
            }
            cnt += __popc(m);
        }
        if (lane == 0) g_cnt[e] = cnt;
    }
    __syncthreads();
    if (threadIdx.x == 0) {
        int off = 0;
        #pragma unroll
        for (int i = 0; i < NEXP; i++) { g_off[i] = off; off += g_cnt[i]; }
    }
}

__global__ void split_x_kernel(const float* __restrict__ x) {
    int i = blockIdx.x * blockDim.x + threadIdx.x;
    float4 v = ((const float4*)x)[i];
    size_t o = (size_t)i * 4;
    float vv[4] = {v.x, v.y, v.z, v.w};
    #pragma unroll
    for (int k = 0; k < 4; k++) {
        __nv_bfloat16 h = __float2bfloat16(vv[k]);
        g_xhi[o + k] = h;
        g_xlo[o + k] = __float2bfloat16(vv[k] - __bfloat162float(h));
    }
}

// ---------------------------------------------------------------------------
// GEMM1: u = x@w1, v = x@w3 (3-term bf16 split), h = silu(u)*v
// 256 threads (4m x 2n warps, 32x32 warp tile). CTA: 128 tokens x 32 h-cols.
// B tile 64 rows: row 2j = w1 col j, row 2j+1 = w3 col j -> (u,v) land in the
// same thread's (d0,d1): SwiGLU fused in registers.
// One __syncthreads per k-iter: store stage s+1 while computing stage s.
// ---------------------------------------------------------------------------
__global__ void __launch_bounds__(256, 2) ffn1_kernel(const float* __restrict__ w1,
                                                      const float* __restrict__ w3) {
    const int e   = blockIdx.z;
    const int cnt = g_cnt[e];
    const int m0  = blockIdx.x * 128;
    if (m0 >= cnt) return;
    const int n0   = blockIdx.y * 32;     // h-cols
    const int base = g_off[e];

    extern __shared__ char sm[];
    const uint32_t sbase = smem_u32(sm);
    const int tid = threadIdx.x, lane = tid & 31, wid = tid >> 5;
    const int wm = wid & 3, wn = wid >> 2;

    const float* w1e = w1 + (size_t)e * DIM_ * HID_;
    const float* w3e = w3 + (size_t)e * DIM_ * HID_;

    // A loader: 1024 uint4 tasks (2 mats x 128 rows x 4 kq), 4/thread
    const __nv_bfloat16* apA[4];
    uint32_t aoA[4];
    #pragma unroll
    for (int q = 0; q < 4; q++) {
        int idx = tid + q * 256;
        int mat = idx >> 9;
        int rem = idx & 511;
        int row = rem >> 2, kq = rem & 3;
        int tok = g_list[e][min(m0 + row, cnt - 1)];
        apA[q] = (mat ? g_xlo : g_xhi) + (size_t)tok * DIM_ + kq * 8;
        aoA[q] = mat * TILE_A + row * ROWB + kq * 16;
    }
    // B loader: 256 tasks (64 rows x 4 k-blocks), 1/thread, 8 fp32 each
    const int bn = tid & 63, bkb = tid >> 6;
    const float* pB = ((bn & 1) ? w3e : w1e) + (size_t)(bkb * 8) * HID_ + (n0 + (bn >> 1));
    const uint32_t boH = OFF_BH + bn * ROWB + bkb * 16;

    const int mi = lane >> 3, lr = lane & 7;
    const uint32_t aLB = (uint32_t)((wm * 32 + (mi & 1) * 8 + lr) * ROWB + (mi >> 1) * 16);
    const uint32_t bLB = (uint32_t)((wn * 32 + (mi >> 1) * 8 + lr) * ROWB + (mi & 1) * 16);

    float acc[2][4][4];
    #pragma unroll
    for (int a = 0; a < 2; a++)
        #pragma unroll
        for (int b = 0; b < 4; b++)
            #pragma unroll
            for (int c = 0; c < 4; c++) acc[a][b][c] = 0.f;

    uint4 pa[4];
    float pf[8];
    // iter 0 -> stage 0
    #pragma unroll
    for (int q = 0; q < 4; q++) pa[q] = *(const uint4*)(apA[q]);
    #pragma unroll
    for (int j = 0; j < 8; j++) pf[j] = pB[(size_t)j * HID_];
    {
        char* st = sm;
        #pragma unroll
        for (int q = 0; q < 4; q++) *(uint4*)(st + aoA[q]) = pa[q];
        uint32_t hp[4], lp[4];
        #pragma unroll
        for (int j = 0; j < 4; j++) split_pair(pf[2*j], pf[2*j+1], hp[j], lp[j]);
        *(uint4*)(st + boH)                   = make_uint4(hp[0], hp[1], hp[2], hp[3]);
        *(uint4*)(st + boH + (OFF_BL-OFF_BH)) = make_uint4(lp[0], lp[1], lp[2], lp[3]);
    }
    __syncthreads();
    // prefetch iter 1
    #pragma unroll
    for (int q = 0; q < 4; q++) pa[q] = *(const uint4*)(apA[q] + 32);
    #pragma unroll
    for (int j = 0; j < 8; j++) pf[j] = pB[(size_t)(32 + j) * HID_];

    const int NCH = DIM_ / 32;   // 64
    for (int i = 0; i < NCH; i++) {
        const uint32_t stS = sbase + (i & 1) * STAGE_B;
        // store stage i+1 (other buffer) from prefetched regs
        if (i + 1 < NCH) {
            char* st = sm + ((i + 1) & 1) * STAGE_B;
            #pragma unroll
            for (int q = 0; q < 4; q++) *(uint4*)(st + aoA[q]) = pa[q];
            uint32_t hp[4], lp[4];
            #pragma unroll
            for (int j = 0; j < 4; j++) split_pair(pf[2*j], pf[2*j+1], hp[j], lp[j]);
            *(uint4*)(st + boH)                   = make_uint4(hp[0], hp[1], hp[2], hp[3]);
            *(uint4*)(st + boH + (OFF_BL-OFF_BH)) = make_uint4(lp[0], lp[1], lp[2], lp[3]);
        }
        if (i + 2 < NCH) {
            int k0n = (i + 2) * 32;
            #pragma unroll
            for (int q = 0; q < 4; q++) pa[q] = *(const uint4*)(apA[q] + k0n);
            #pragma unroll
            for (int j = 0; j < 8; j++) pf[j] = pB[(size_t)(k0n + j) * HID_];
        }
        // compute stage i
        #pragma unroll
        for (int ks = 0; ks < 2; ks++) {
            uint32_t ah[2][4], al[2][4], bh[2][4], bl[2][4];
            #pragma unroll
            for (int mt = 0; mt < 2; mt++) {
                LDM_X4(ah[mt], stS + OFF_AH + aLB + mt * (16 * ROWB) + ks * 32);
                LDM_X4(al[mt], stS + OFF_AL + aLB + mt * (16 * ROWB) + ks * 32);
            }
            #pragma unroll
            for (int ng = 0; ng < 2; ng++) {
                LDM_X4(bh[ng], stS + OFF_BH + bLB + ng * (16 * ROWB) + ks * 32);
                LDM_X4(bl[ng], stS + OFF_BL + bLB + ng * (16 * ROWB) + ks * 32);
            }
            #pragma unroll
            for (int mt = 0; mt < 2; mt++)
                #pragma unroll
                for (int ng = 0; ng < 2; ng++)
                    #pragma unroll
                    for (int h2 = 0; h2 < 2; h2++) {
                        int nt = ng * 2 + h2;
                        MMA_BF16(acc[mt][nt], ah[mt], bh[ng][2*h2], bh[ng][2*h2+1]);
                        MMA_BF16(acc[mt][nt], al[mt], bh[ng][2*h2], bh[ng][2*h2+1]);
                        MMA_BF16(acc[mt][nt], ah[mt], bl[ng][2*h2], bl[ng][2*h2+1]);
                    }
        }
        __syncthreads();
    }

    // epilogue: d0=u, d1=v for the same h-col, in-register SwiGLU
    #pragma unroll
    for (int mt = 0; mt < 2; mt++)
        #pragma unroll
        for (int nt = 0; nt < 4; nt++) {
            int j = wn * 16 + nt * 4 + (lane & 3);   // h-col within 32
            #pragma unroll
            for (int rr = 0; rr < 2; rr++) {
                int r  = wm * 32 + mt * 16 + (lane >> 2) + rr * 8;
                int gm = m0 + r;
                float u = acc[mt][nt][2*rr], v = acc[mt][nt][2*rr+1];
                float h = u / (1.f + __expf(-u)) * v;
                __nv_bfloat16 hh = __float2bfloat16(h);
                __nv_bfloat16 hl = __float2bfloat16(h - __bfloat162float(hh));
                if (gm < cnt) {
                    size_t dst = (size_t)(base + gm) * HID_ + n0 + j;
                    g_hh[dst] = hh;
                    g_hl[dst] = hl;
                }
            }
        }
}

// ---------------------------------------------------------------------------
// GEMM2: y = h @ w2 (3-term split).  256 threads, CTA 128 x 64, BK=32.
// ---------------------------------------------------------------------------
__global__ void __launch_bounds__(256, 2) ffn2_kernel(const float* __restrict__ w2) {
    const int e   = blockIdx.z;
    const int cnt = g_cnt[e];
    const int m0  = blockIdx.x * 128;
    if (m0 >= cnt) return;
    const int n0   = blockIdx.y * 64;
    const int base = g_off[e];

    extern __shared__ char sm[];
    const uint32_t sbase = smem_u32(sm);
    const int tid = threadIdx.x, lane = tid & 31, wid = tid >> 5;
    const int wm = wid & 3, wn = wid >> 2;

    const float* w2e = w2 + (size_t)e * HID_ * DIM_;

    const __nv_bfloat16* apA[4];
    uint32_t aoA[4];
    #pragma unroll
    for (int q = 0; q < 4; q++) {
        int idx = tid + q * 256;
        int mat = idx >> 9;
        int rem = idx & 511;
        int row = rem >> 2, kq = rem & 3;
        int r   = base + min(m0 + row, cnt - 1);
        apA[q] = (mat ? g_hl : g_hh) + (size_t)r * HID_ + kq * 8;
        aoA[q] = mat * TILE_A + row * ROWB + kq * 16;
    }
    const int bn = tid & 63, bkb = tid >> 6;
    const float* pB = w2e + (size_t)(bkb * 8) * DIM_ + (n0 + bn);
    const uint32_t boH = OFF_BH + bn * ROWB + bkb * 16;

    const int mi = lane >> 3, lr = lane & 7;
    const uint32_t aLB = (uint32_t)((wm * 32 + (mi & 1) * 8 + lr) * ROWB + (mi >> 1) * 16);
    const uint32_t bLB = (uint32_t)((wn * 32 + (mi >> 1) * 8 + lr) * ROWB + (mi & 1) * 16);

    float acc[2][4][4];
    #pragma unroll
    for (int a = 0; a < 2; a++)
        #pragma unroll
        for (int b = 0; b < 4; b++)
            #pragma unroll
            for (int c = 0; c < 4; c++) acc[a][b][c] = 0.f;

    uint4 pa[4];
    float pf[8];
    #pragma unroll
    for (int q = 0; q < 4; q++) pa[q] = *(const uint4*)(apA[q]);
    #pragma unroll
    for (int j = 0; j < 8; j++) pf[j] = pB[(size_t)j * DIM_];
    {
        char* st = sm;
        #pragma unroll
        for (int q = 0; q < 4; q++) *(uint4*)(st + aoA[q]) = pa[q];
        uint32_t hp[4], lp[4];
        #pragma unroll
        for (int j = 0; j < 4; j++) split_pair(pf[2*j], pf[2*j+1], hp[j], lp[j]);
        *(uint4*)(st + boH)                   = make_uint4(hp[0], hp[1], hp[2], hp[3]);
        *(uint4*)(st + boH + (OFF_BL-OFF_BH)) = make_uint4(lp[0], lp[1], lp[2], lp[3]);
    }
    __syncthreads();
    #pragma unroll
    for (int q = 0; q < 4; q++) pa[q] = *(const uint4*)(apA[q] + 32);
    #pragma unroll
    for (int j = 0; j < 8; j++) pf[j] = pB[(size_t)(32 + j) * DIM_];

    const int NCH = HID_ / 32;   // 176
    for (int i = 0; i < NCH; i++) {
        const uint32_t stS = sbase + (i & 1) * STAGE_B;
        if (i + 1 < NCH) {
            char* st = sm + ((i + 1) & 1) * STAGE_B;
            #pragma unroll
            for (int q = 0; q < 4; q++) *(uint4*)(st + aoA[q]) = pa[q];
            uint32_t hp[4], lp[4];
            #pragma unroll
            for (int j = 0; j < 4; j++) split_pair(pf[2*j], pf[2*j+1], hp[j], lp[j]);
            *(uint4*)(st + boH)                   = make_uint4(hp[0], hp[1], hp[2], hp[3]);
            *(uint4*)(st + boH + (OFF_BL-OFF_BH)) = make_uint4(lp[0], lp[1], lp[2], lp[3]);
        }
        if (i + 2 < NCH) {
            int k0n = (i + 2) * 32;
            #pragma unroll
            for (int q = 0; q < 4; q++) pa[q] = *(const uint4*)(apA[q] + k0n);
            #pragma unroll
            for (int j = 0; j < 8; j++) pf[j] = pB[(size_t)(k0n + j) * DIM_];
        }
        #pragma unroll
        for (int ks = 0; ks < 2; ks++) {
            uint32_t ah[2][4], al[2][4], bh[2][4], bl[2][4];
            #pragma unroll
            for (int mt = 0; mt < 2; mt++) {
                LDM_X4(ah[mt], stS + OFF_AH + aLB + mt * (16 * ROWB) + ks * 32);
                LDM_X4(al[mt], stS + OFF_AL + aLB + mt * (16 * ROWB) + ks * 32);
            }
            #pragma unroll
            for (int ng = 0; ng < 2; ng++) {
                LDM_X4(bh[ng], stS + OFF_BH + bLB + ng * (16 * ROWB) + ks * 32);
                LDM_X4(bl[ng], stS + OFF_BL + bLB + ng * (16 * ROWB) + ks * 32);
            }
            #pragma unroll
            for (int mt = 0; mt < 2; mt++)
                #pragma unroll
                for (int ng = 0; ng < 2; ng++)
                    #pragma unroll
                    for (int h2 = 0; h2 < 2; h2++) {
                        int nt = ng * 2 + h2;
                        MMA_BF16(acc[mt][nt], ah[mt], bh[ng][2*h2], bh[ng][2*h2+1]);
                        MMA_BF16(acc[mt][nt], al[mt], bh[ng][2*h2], bh[ng][2*h2+1]);
                        MMA_BF16(acc[mt][nt], ah[mt], bl[ng][2*h2], bl[ng][2*h2+1]);
                    }
        }
        __syncthreads();
    }

    #pragma unroll
    for (int mt = 0; mt < 2; mt++)
        #pragma unroll
        for (int nt = 0; nt < 4; nt++) {
            int c = wn * 32 + nt * 8 + (lane & 3) * 2;
            #pragma unroll
            for (int rr = 0; rr < 2; rr++) {
                int r  = wm * 32 + mt * 16 + (lane >> 2) + rr * 8;
                int gm = m0 + r;
                if (gm < cnt) {
                    size_t dst = (size_t)(base + gm) * DIM_ + n0 + c;
                    *(float2*)(g_y + dst) = make_float2(acc[mt][nt][2*rr], acc[mt][nt][2*rr+1]);
                }
            }
        }
}

// ---------------------------------------------------------------------------
// Combine
// ---------------------------------------------------------------------------
__global__ void combine_kernel(float* __restrict__ out) {
    const int t  = blockIdx.x;
    const int e0 = g_eid[t][0];
    const int e1 = g_eid[t][1];
    const int n0 = g_off[e0] + g_pos[t][0];
    const int n1 = g_off[e1] + g_pos[t][1];
    const float w0 = g_ew[t][0];
    const float w1 = g_ew[t][1];
    const float* y0 = &g_y[(size_t)n0 * DIM_];
    const float* y1 = &g_y[(size_t)n1 * DIM_];
    float* op = out + (size_t)t * DIM_;
    for (int d = threadIdx.x * 4; d < DIM_; d += blockDim.x * 4) {
        float4 a = *(const float4*)(y0 + d);
        float4 b = *(const float4*)(y1 + d);
        *(float4*)(op + d) = make_float4(w0 * a.x + w1 * b.x, w0 * a.y + w1 * b.y,
                                         w0 * a.z + w1 * b.z, w0 * a.w + w1 * b.w);
    }
}

// ---------------------------------------------------------------------------
// Entry point
// ---------------------------------------------------------------------------
extern "C" void kernel_launch(void* const* d_in, const int* in_sizes, int n_in,
                              void* d_out, int out_size) {
    const float* x  = (const float*)d_in[0];
    const float* gw = (const float*)d_in[1];
    const float* w1 = (const float*)d_in[2];
    const float* w2 = (const float*)d_in[3];
    const float* w3 = (const float*)d_in[4];
    float* out = (float*)d_out;

    cudaFuncSetAttribute(ffn1_kernel, cudaFuncAttributeMaxDynamicSharedMemorySize, SMEM_TOT);
    cudaFuncSetAttribute(ffn2_kernel, cudaFuncAttributeMaxDynamicSharedMemorySize, SMEM_TOT);

    gate_kernel<<<T_TOKENS, 256>>>(x, gw);
    route_kernel<<<1, 256>>>();
    split_x_kernel<<<(T_TOKENS * DIM_ / 4) / 256, 256>>>(x);
    ffn1_kernel<<<dim3(T_TOKENS / 128, HID_ / 32, NEXP), 256, SMEM_TOT>>>(w1, w3);
    ffn2_kernel<<<dim3(T_TOKENS / 128, DIM_ / 64, NEXP), 256, SMEM_TOT>>>(w2);
    combine_kernel<<<T_TOKENS, 256>>>(out);
}

// round 6
// speedup vs baseline: 2.5191x; 1.1045x over previous
#include <cuda_runtime.h>
#include <cuda_bf16.h>
#include <cstdint>

#define T_TOKENS 2048
#define DIM_     2048
#define HID_     5632
#define NEXP     8
#define NENT     (T_TOKENS * 2)

// ---------------------------------------------------------------------------
// Scratch (device globals — no cudaMalloc allowed)
// ---------------------------------------------------------------------------
__device__ int   g_eid [T_TOKENS][2];
__device__ float g_ew  [T_TOKENS][2];
__device__ int   g_pos [T_TOKENS][2];
__device__ int   g_list[NEXP][T_TOKENS];
__device__ int   g_cnt [NEXP];
__device__ int   g_off [NEXP];
__device__ __nv_bfloat16 g_xhi[(size_t)T_TOKENS * DIM_];
__device__ __nv_bfloat16 g_xlo[(size_t)T_TOKENS * DIM_];
__device__ __nv_bfloat16 g_hh [(size_t)NENT * HID_];
__device__ __nv_bfloat16 g_hl [(size_t)NENT * HID_];
__device__ float         g_y  [(size_t)NENT * DIM_];

// ---------------------------------------------------------------------------
// Helpers
// ---------------------------------------------------------------------------
__device__ __forceinline__ uint32_t smem_u32(const void* p) {
    uint32_t a;
    asm("{ .reg .u64 t; cvta.to.shared.u64 t, %1; cvt.u32.u64 %0, t; }" : "=r"(a) : "l"(p));
    return a;
}
__device__ __forceinline__ uint32_t pkbf(__nv_bfloat16 a, __nv_bfloat16 b) {
    return (uint32_t)__bfloat16_as_ushort(a) | ((uint32_t)__bfloat16_as_ushort(b) << 16);
}
__device__ __forceinline__ void split_pair(float f0, float f1, uint32_t& hp, uint32_t& lp) {
    __nv_bfloat16 h0 = __float2bfloat16(f0);
    __nv_bfloat16 h1 = __float2bfloat16(f1);
    __nv_bfloat16 l0 = __float2bfloat16(f0 - __bfloat162float(h0));
    __nv_bfloat16 l1 = __float2bfloat16(f1 - __bfloat162float(h1));
    hp = pkbf(h0, h1);
    lp = pkbf(l0, l1);
}

#define LDM_X4(r, addr)                                                          \
    asm volatile("ldmatrix.sync.aligned.m8n8.x4.shared.b16 {%0,%1,%2,%3}, [%4];" \
        : "=r"((r)[0]), "=r"((r)[1]), "=r"((r)[2]), "=r"((r)[3]) : "r"(addr))

#define MMA_BF16(d, a, b0, b1)                                                   \
    asm volatile("mma.sync.aligned.m16n8k16.row.col.f32.bf16.bf16.f32 "          \
        "{%0,%1,%2,%3}, {%4,%5,%6,%7}, {%8,%9}, {%0,%1,%2,%3};"                  \
        : "+f"((d)[0]), "+f"((d)[1]), "+f"((d)[2]), "+f"((d)[3])                 \
        : "r"((a)[0]), "r"((a)[1]), "r"((a)[2]), "r"((a)[3]), "r"(b0), "r"(b1))

#define CP_ASYNC16(dst, src)                                                     \
    asm volatile("cp.async.cg.shared.global [%0], [%1], 16;" :: "r"(dst), "l"(src))
#define CP_COMMIT() asm volatile("cp.async.commit_group;" ::: "memory")
#define CP_WAIT0()  asm volatile("cp.async.wait_group 0;" ::: "memory")

// Smem geometry: rows of 32 bf16 padded to 80B -> conflict-free ldmatrix.
#define ROWB    80
#define TILE_A  10240           // 128 rows * 80B (one A matrix: hi or lo)
#define OFF_AH  0
#define OFF_AL  10240
#define OFF_BH  20480
#define OFF_BL  25600
#define STAGE_B 30720
#define SMEM_TOT (2 * STAGE_B)  // 61440; 3 CTAs/SM = 180KB < 228KB

// ---------------------------------------------------------------------------
// Gating + routing + x split
// ---------------------------------------------------------------------------
__global__ void gate_kernel(const float* __restrict__ x, const float* __restrict__ gw) {
    const int t = blockIdx.x, lane = threadIdx.x & 31, w = threadIdx.x >> 5;
    const float* xr = x + (size_t)t * DIM_;
    const float* gr = gw + (size_t)w * DIM_;
    float s = 0.f;
    for (int d = lane * 4; d < DIM_; d += 128) {
        float4 a = *(const float4*)(xr + d);
        float4 b = *(const float4*)(gr + d);
        s += a.x * b.x + a.y * b.y + a.z * b.z + a.w * b.w;
    }
    #pragma unroll
    for (int o = 16; o; o >>= 1) s += __shfl_xor_sync(0xffffffffu, s, o);
    __shared__ float sc[NEXP];
    if (lane == 0) sc[w] = s;
    __syncthreads();
    if (threadIdx.x == 0) {
        int b0 = 0; float s0 = sc[0];
        #pragma unroll
        for (int e = 1; e < NEXP; e++) if (sc[e] > s0) { s0 = sc[e]; b0 = e; }
        int b1 = -1; float s1 = -1e30f;
        #pragma unroll
        for (int e = 0; e < NEXP; e++) if (e != b0 && sc[e] > s1) { s1 = sc[e]; b1 = e; }
        float e1 = __expf(s1 - s0);
        float inv = 1.f / (1.f + e1);
        g_eid[t][0] = b0; g_eid[t][1] = b1;
        g_ew [t][0] = inv; g_ew [t][1] = e1 * inv;
    }
}

__global__ void route_kernel() {
    const int lane = threadIdx.x & 31, e = threadIdx.x >> 5;
    if (e < NEXP) {
        int cnt = 0;
        for (int t0 = 0; t0 < T_TOKENS; t0 += 32) {
            int t = t0 + lane;
            int e0 = g_eid[t][0], e1 = g_eid[t][1];
            bool sel = (e0 == e) || (e1 == e);
            int slot = (e0 == e) ? 0 : 1;
            unsigned m = __ballot_sync(0xffffffffu, sel);
            if (sel) {
                int p = cnt + __popc(m & ((1u << lane) - 1u));
                g_list[e][p] = t;
                g_pos[t][slot] = p;
            }
            cnt += __popc(m);
        }
        if (lane == 0) g_cnt[e] = cnt;
    }
    __syncthreads();
    if (threadIdx.x == 0) {
        int off = 0;
        #pragma unroll
        for (int i = 0; i < NEXP; i++) { g_off[i] = off; off += g_cnt[i]; }
    }
}

__global__ void split_x_kernel(const float* __restrict__ x) {
    int i = blockIdx.x * blockDim.x + threadIdx.x;
    float4 v = ((const float4*)x)[i];
    size_t o = (size_t)i * 4;
    float vv[4] = {v.x, v.y, v.z, v.w};
    #pragma unroll
    for (int k = 0; k < 4; k++) {
        __nv_bfloat16 h = __float2bfloat16(vv[k]);
        g_xhi[o + k] = h;
        g_xlo[o + k] = __float2bfloat16(vv[k] - __bfloat162float(h));
    }
}

// ---------------------------------------------------------------------------
// GEMM1: u = x@w1, v = x@w3 (3-term bf16 split), h = silu(u)*v
// 128 threads = 4 warps (2m x 2n), warp tile 64x32. CTA: 128 tokens x 32 h-cols.
// A tiles via cp.async (pre-split bf16 in global). B interleaved (u,v in d0,d1).
// One __syncthreads per k-iter.
// ---------------------------------------------------------------------------
__global__ void __launch_bounds__(128, 3) ffn1_kernel(const float* __restrict__ w1,
                                                      const float* __restrict__ w3) {
    const int e   = blockIdx.z;
    const int cnt = g_cnt[e];
    const int m0  = blockIdx.x * 128;
    if (m0 >= cnt) return;
    const int n0   = blockIdx.y * 32;     // h-cols
    const int base = g_off[e];

    extern __shared__ char sm[];
    const uint32_t sbase = smem_u32(sm);
    const int tid = threadIdx.x, lane = tid & 31, wid = tid >> 5;
    const int wm = wid & 1, wn = wid >> 1;

    const float* w1e = w1 + (size_t)e * DIM_ * HID_;
    const float* w3e = w3 + (size_t)e * DIM_ * HID_;

    // A loader: 1024 cp.async tasks (2 mats x 128 rows x 4 kq), 8/thread
    const __nv_bfloat16* apA[8];
    uint32_t aoA[8];
    #pragma unroll
    for (int q = 0; q < 8; q++) {
        int idx = tid + q * 128;
        int mat = idx >> 9;
        int rem = idx & 511;
        int row = rem >> 2, kq = rem & 3;
        int tok = g_list[e][min(m0 + row, cnt - 1)];
        apA[q] = (mat ? g_xlo : g_xhi) + (size_t)tok * DIM_ + kq * 8;
        aoA[q] = mat * TILE_A + row * ROWB + kq * 16;
    }
    // B loader: 256 tasks (64 interleaved rows x 4 k-blocks), 2/thread
    int bnT[2], bkT[2];
    const float* pB[2];
    #pragma unroll
    for (int r = 0; r < 2; r++) {
        int task = tid + r * 128;
        bnT[r] = task & 63;
        bkT[r] = task >> 6;
        pB[r]  = ((bnT[r] & 1) ? w3e : w1e) + (size_t)(bkT[r] * 8) * HID_ + (n0 + (bnT[r] >> 1));
    }

    const int mi = lane >> 3, lr = lane & 7;
    const uint32_t aLB = (uint32_t)((wm * 64 + (mi & 1) * 8 + lr) * ROWB + (mi >> 1) * 16);
    const uint32_t bLB = (uint32_t)((wn * 32 + (mi >> 1) * 8 + lr) * ROWB + (mi & 1) * 16);

    float acc[4][4][4];
    #pragma unroll
    for (int a = 0; a < 4; a++)
        #pragma unroll
        for (int b = 0; b < 4; b++)
            #pragma unroll
            for (int c = 0; c < 4; c++) acc[a][b][c] = 0.f;

    float pf[2][8];
    // ---- prologue: stage 0 ----
    #pragma unroll
    for (int q = 0; q < 8; q++) CP_ASYNC16(sbase + aoA[q], apA[q]);
    CP_COMMIT();
    #pragma unroll
    for (int r = 0; r < 2; r++)
        #pragma unroll
        for (int j = 0; j < 8; j++) pf[r][j] = pB[r][(size_t)j * HID_];
    #pragma unroll
    for (int r = 0; r < 2; r++) {
        uint32_t hp[4], lp[4];
        #pragma unroll
        for (int j = 0; j < 4; j++) split_pair(pf[r][2*j], pf[r][2*j+1], hp[j], lp[j]);
        uint32_t bo = bnT[r] * ROWB + bkT[r] * 16;
        *(uint4*)(sm + OFF_BH + bo) = make_uint4(hp[0], hp[1], hp[2], hp[3]);
        *(uint4*)(sm + OFF_BL + bo) = make_uint4(lp[0], lp[1], lp[2], lp[3]);
    }
    CP_WAIT0();
    __syncthreads();
    // prefetch B regs for iter 1
    #pragma unroll
    for (int r = 0; r < 2; r++)
        #pragma unroll
        for (int j = 0; j < 8; j++) pf[r][j] = pB[r][(size_t)(32 + j) * HID_];

    const int NCH = DIM_ / 32;   // 64
    for (int i = 0; i < NCH; i++) {
        const uint32_t stS = sbase + (i & 1) * STAGE_B;
        // fill stage i+1 while computing stage i
        if (i + 1 < NCH) {
            const uint32_t stN = sbase + ((i + 1) & 1) * STAGE_B;
            char* stNc = sm + ((i + 1) & 1) * STAGE_B;
            int k0n = (i + 1) * 32;
            #pragma unroll
            for (int q = 0; q < 8; q++) CP_ASYNC16(stN + aoA[q], apA[q] + k0n);
            CP_COMMIT();
            #pragma unroll
            for (int r = 0; r < 2; r++) {
                uint32_t hp[4], lp[4];
                #pragma unroll
                for (int j = 0; j < 4; j++) split_pair(pf[r][2*j], pf[r][2*j+1], hp[j], lp[j]);
                uint32_t bo = bnT[r] * ROWB + bkT[r] * 16;
                *(uint4*)(stNc + OFF_BH + bo) = make_uint4(hp[0], hp[1], hp[2], hp[3]);
                *(uint4*)(stNc + OFF_BL + bo) = make_uint4(lp[0], lp[1], lp[2], lp[3]);
            }
        }
        if (i + 2 < NCH) {
            int k0p = (i + 2) * 32;
            #pragma unroll
            for (int r = 0; r < 2; r++)
                #pragma unroll
                for (int j = 0; j < 8; j++) pf[r][j] = pB[r][(size_t)(k0p + j) * HID_];
        }
        // compute stage i
        #pragma unroll
        for (int ks = 0; ks < 2; ks++) {
            uint32_t bh[2][4], bl[2][4];
            #pragma unroll
            for (int ng = 0; ng < 2; ng++) {
                LDM_X4(bh[ng], stS + OFF_BH + bLB + ng * (16 * ROWB) + ks * 32);
                LDM_X4(bl[ng], stS + OFF_BL + bLB + ng * (16 * ROWB) + ks * 32);
            }
            #pragma unroll
            for (int mt = 0; mt < 4; mt++) {
                uint32_t ah[4], al[4];
                LDM_X4(ah, stS + OFF_AH + aLB + mt * (16 * ROWB) + ks * 32);
                LDM_X4(al, stS + OFF_AL + aLB + mt * (16 * ROWB) + ks * 32);
                #pragma unroll
                for (int ng = 0; ng < 2; ng++)
                    #pragma unroll
                    for (int h2 = 0; h2 < 2; h2++) {
                        int nt = ng * 2 + h2;
                        MMA_BF16(acc[mt][nt], ah, bh[ng][2*h2], bh[ng][2*h2+1]);
                        MMA_BF16(acc[mt][nt], al, bh[ng][2*h2], bh[ng][2*h2+1]);
                        MMA_BF16(acc[mt][nt], ah, bl[ng][2*h2], bl[ng][2*h2+1]);
                    }
            }
        }
        CP_WAIT0();
        __syncthreads();
    }

    // epilogue: d0=u, d1=v for the same h-col, in-register SwiGLU
    #pragma unroll
    for (int mt = 0; mt < 4; mt++)
        #pragma unroll
        for (int nt = 0; nt < 4; nt++) {
            int j = wn * 16 + nt * 4 + (lane & 3);
            #pragma unroll
            for (int rr = 0; rr < 2; rr++) {
                int r  = wm * 64 + mt * 16 + (lane >> 2) + rr * 8;
                int gm = m0 + r;
                float u = acc[mt][nt][2*rr], v = acc[mt][nt][2*rr+1];
                float h = u / (1.f + __expf(-u)) * v;
                __nv_bfloat16 hh = __float2bfloat16(h);
                __nv_bfloat16 hl = __float2bfloat16(h - __bfloat162float(hh));
                if (gm < cnt) {
                    size_t dst = (size_t)(base + gm) * HID_ + n0 + j;
                    g_hh[dst] = hh;
                    g_hl[dst] = hl;
                }
            }
        }
}

// ---------------------------------------------------------------------------
// GEMM2: y = h @ w2 (3-term split). 128 threads, warp tile 64x32, CTA 128x64.
// ---------------------------------------------------------------------------
__global__ void __launch_bounds__(128, 3) ffn2_kernel(const float* __restrict__ w2) {
    const int e   = blockIdx.z;
    const int cnt = g_cnt[e];
    const int m0  = blockIdx.x * 128;
    if (m0 >= cnt) return;
    const int n0   = blockIdx.y * 64;
    const int base = g_off[e];

    extern __shared__ char sm[];
    const uint32_t sbase = smem_u32(sm);
    const int tid = threadIdx.x, lane = tid & 31, wid = tid >> 5;
    const int wm = wid & 1, wn = wid >> 1;

    const float* w2e = w2 + (size_t)e * HID_ * DIM_;

    const __nv_bfloat16* apA[8];
    uint32_t aoA[8];
    #pragma unroll
    for (int q = 0; q < 8; q++) {
        int idx = tid + q * 128;
        int mat = idx >> 9;
        int rem = idx & 511;
        int row = rem >> 2, kq = rem & 3;
        int r   = base + min(m0 + row, cnt - 1);
        apA[q] = (mat ? g_hl : g_hh) + (size_t)r * HID_ + kq * 8;
        aoA[q] = mat * TILE_A + row * ROWB + kq * 16;
    }
    int bnT[2], bkT[2];
    const float* pB[2];
    #pragma unroll
    for (int r = 0; r < 2; r++) {
        int task = tid + r * 128;
        bnT[r] = task & 63;
        bkT[r] = task >> 6;
        pB[r]  = w2e + (size_t)(bkT[r] * 8) * DIM_ + (n0 + bnT[r]);
    }

    const int mi = lane >> 3, lr = lane & 7;
    const uint32_t aLB = (uint32_t)((wm * 64 + (mi & 1) * 8 + lr) * ROWB + (mi >> 1) * 16);
    const uint32_t bLB = (uint32_t)((wn * 32 + (mi >> 1) * 8 + lr) * ROWB + (mi & 1) * 16);

    float acc[4][4][4];
    #pragma unroll
    for (int a = 0; a < 4; a++)
        #pragma unroll
        for (int b = 0; b < 4; b++)
            #pragma unroll
            for (int c = 0; c < 4; c++) acc[a][b][c] = 0.f;

    float pf[2][8];
    #pragma unroll
    for (int q = 0; q < 8; q++) CP_ASYNC16(sbase + aoA[q], apA[q]);
    CP_COMMIT();
    #pragma unroll
    for (int r = 0; r < 2; r++)
        #pragma unroll
        for (int j = 0; j < 8; j++) pf[r][j] = pB[r][(size_t)j * DIM_];
    #pragma unroll
    for (int r = 0; r < 2; r++) {
        uint32_t hp[4], lp[4];
        #pragma unroll
        for (int j = 0; j < 4; j++) split_pair(pf[r][2*j], pf[r][2*j+1], hp[j], lp[j]);
        uint32_t bo = bnT[r] * ROWB + bkT[r] * 16;
        *(uint4*)(sm + OFF_BH + bo) = make_uint4(hp[0], hp[1], hp[2], hp[3]);
        *(uint4*)(sm + OFF_BL + bo) = make_uint4(lp[0], lp[1], lp[2], lp[3]);
    }
    CP_WAIT0();
    __syncthreads();
    #pragma unroll
    for (int r = 0; r < 2; r++)
        #pragma unroll
        for (int j = 0; j < 8; j++) pf[r][j] = pB[r][(size_t)(32 + j) * DIM_];

    const int NCH = HID_ / 32;   // 176
    for (int i = 0; i < NCH; i++) {
        const uint32_t stS = sbase + (i & 1) * STAGE_B;
        if (i + 1 < NCH) {
            const uint32_t stN = sbase + ((i + 1) & 1) * STAGE_B;
            char* stNc = sm + ((i + 1) & 1) * STAGE_B;
            int k0n = (i + 1) * 32;
            #pragma unroll
            for (int q = 0; q < 8; q++) CP_ASYNC16(stN + aoA[q], apA[q] + k0n);
            CP_COMMIT();
            #pragma unroll
            for (int r = 0; r < 2; r++) {
                uint32_t hp[4], lp[4];
                #pragma unroll
                for (int j = 0; j < 4; j++) split_pair(pf[r][2*j], pf[r][2*j+1], hp[j], lp[j]);
                uint32_t bo = bnT[r] * ROWB + bkT[r] * 16;
                *(uint4*)(stNc + OFF_BH + bo) = make_uint4(hp[0], hp[1], hp[2], hp[3]);
                *(uint4*)(stNc + OFF_BL + bo) = make_uint4(lp[0], lp[1], lp[2], lp[3]);
            }
        }
        if (i + 2 < NCH) {
            int k0p = (i + 2) * 32;
            #pragma unroll
            for (int r = 0; r < 2; r++)
                #pragma unroll
                for (int j = 0; j < 8; j++) pf[r][j] = pB[r][(size_t)(k0p + j) * DIM_];
        }
        #pragma unroll
        for (int ks = 0; ks < 2; ks++) {
            uint32_t bh[2][4], bl[2][4];
            #pragma unroll
            for (int ng = 0; ng < 2; ng++) {
                LDM_X4(bh[ng], stS + OFF_BH + bLB + ng * (16 * ROWB) + ks * 32);
                LDM_X4(bl[ng], stS + OFF_BL + bLB + ng * (16 * ROWB) + ks * 32);
            }
            #pragma unroll
            for (int mt = 0; mt < 4; mt++) {
                uint32_t ah[4], al[4];
                LDM_X4(ah, stS + OFF_AH + aLB + mt * (16 * ROWB) + ks * 32);
                LDM_X4(al, stS + OFF_AL + aLB + mt * (16 * ROWB) + ks * 32);
                #pragma unroll
                for (int ng = 0; ng < 2; ng++)
                    #pragma unroll
                    for (int h2 = 0; h2 < 2; h2++) {
                        int nt = ng * 2 + h2;
                        MMA_BF16(acc[mt][nt], ah, bh[ng][2*h2], bh[ng][2*h2+1]);
                        MMA_BF16(acc[mt][nt], al, bh[ng][2*h2], bh[ng][2*h2+1]);
                        MMA_BF16(acc[mt][nt], ah, bl[ng][2*h2], bl[ng][2*h2+1]);
                    }
            }
        }
        CP_WAIT0();
        __syncthreads();
    }

    #pragma unroll
    for (int mt = 0; mt < 4; mt++)
        #pragma unroll
        for (int nt = 0; nt < 4; nt++) {
            int c = wn * 32 + nt * 8 + (lane & 3) * 2;
            #pragma unroll
            for (int rr = 0; rr < 2; rr++) {
                int r  = wm * 64 + mt * 16 + (lane >> 2) + rr * 8;
                int gm = m0 + r;
                if (gm < cnt) {
                    size_t dst = (size_t)(base + gm) * DIM_ + n0 + c;
                    *(float2*)(g_y + dst) = make_float2(acc[mt][nt][2*rr], acc[mt][nt][2*rr+1]);
                }
            }
        }
}

// ---------------------------------------------------------------------------
// Combine
// ---------------------------------------------------------------------------
__global__ void combine_kernel(float* __restrict__ out) {
    const int t  = blockIdx.x;
    const int e0 = g_eid[t][0];
    const int e1 = g_eid[t][1];
    const int n0 = g_off[e0] + g_pos[t][0];
    const int n1 = g_off[e1] + g_pos[t][1];
    const float w0 = g_ew[t][0];
    const float w1 = g_ew[t][1];
    const float* y0 = &g_y[(size_t)n0 * DIM_];
    const float* y1 = &g_y[(size_t)n1 * DIM_];
    float* op = out + (size_t)t * DIM_;
    for (int d = threadIdx.x * 4; d < DIM_; d += blockDim.x * 4) {
        float4 a = *(const float4*)(y0 + d);
        float4 b = *(const float4*)(y1 + d);
        *(float4*)(op + d) = make_float4(w0 * a.x + w1 * b.x, w0 * a.y + w1 * b.y,
                                         w0 * a.z + w1 * b.z, w0 * a.w + w1 * b.w);
    }
}

// ---------------------------------------------------------------------------
// Entry point
// ---------------------------------------------------------------------------
extern "C" void kernel_launch(void* const* d_in, const int* in_sizes, int n_in,
                              void* d_out, int out_size) {
    const float* x  = (const float*)d_in[0];
    const float* gw = (const float*)d_in[1];
    const float* w1 = (const float*)d_in[2];
    const float* w2 = (const float*)d_in[3];
    const float* w3 = (const float*)d_in[4];
    float* out = (float*)d_out;

    cudaFuncSetAttribute(ffn1_kernel, cudaFuncAttributeMaxDynamicSharedMemorySize, SMEM_TOT);
    cudaFuncSetAttribute(ffn2_kernel, cudaFuncAttributeMaxDynamicSharedMemorySize, SMEM_TOT);

    gate_kernel<<<T_TOKENS, 256>>>(x, gw);
    route_kernel<<<1, 256>>>();
    split_x_kernel<<<(T_TOKENS * DIM_ / 4) / 256, 256>>>(x);
    ffn1_kernel<<<dim3(T_TOKENS / 128, HID_ / 32, NEXP), 128, SMEM_TOT>>>(w1, w3);
    ffn2_kernel<<<dim3(T_TOKENS / 128, DIM_ / 64, NEXP), 128, SMEM_TOT>>>(w2);
    combine_kernel<<<T_TOKENS, 256>>>(out);
}